// round 5
// baseline (speedup 1.0000x reference)
#include <cuda_runtime.h>

#define BB 2
#define DM 192
#define DI 384
#define DS 16
#define DR 12
#define HH 64
#define WW 64
#define LL 4096
#define NROWS (BB*LL)   // 8192

// ---------------- scratch ----------------
__device__ float  g_xa_pre[BB*DI*LL];   // xz first half, NCHW
__device__ float  g_c_pre [BB*DI*LL];
__device__ float  g_xa_conv[BB*DI*LL];  // silu(dwconv(xa))
__device__ float  g_c_conv [BB*DI*LL];
__device__ float  g_z     [NROWS*DI];   // silu(z), (b*l, d)
__device__ float2 g_du    [BB*LL*DI];   // (delta, u) in scan order [b][j][d]
__device__ float2 g_bc    [BB*LL*DS];   // (B_n, C_n) in scan order [b][j][n]
__device__ float  g_y     [NROWS*DI];   // scan output, spatial order, (b*l, d)
__device__ float  g_yz    [NROWS*DI];

__device__ __forceinline__ float silu_f(float v){ return v / (1.f + __expf(-v)); }

__device__ __forceinline__ void cpa8(unsigned dst, const void* src){
    asm volatile("cp.async.ca.shared.global [%0], [%1], 8;\n" :: "r"(dst), "l"(src));
}
__device__ __forceinline__ void cpa16(unsigned dst, const void* src){
    asm volatile("cp.async.ca.shared.global [%0], [%1], 16;\n" :: "r"(dst), "l"(src));
}
__device__ __forceinline__ void cp_commit(){ asm volatile("cp.async.commit_group;\n"); }
__device__ __forceinline__ void cp_wait1(){ asm volatile("cp.async.wait_group 1;\n"); }
__device__ __forceinline__ void cp_wait0(){ asm volatile("cp.async.wait_group 0;\n"); }

// =======================================================================
// gemm128: C[M,N] = A[M,K] * B[N,K]^T.  128x128 tile, 256 thr, 8x8 micro.
// MODE 0: xz  (n0<DI -> xa NCHW via transpose; else silu(z) row-major)
// MODE 1: cond -> NCHW via transpose
// =======================================================================
#define GS 132   // smem row stride (floats), %4==0 for float4

template<int MODE>
__global__ void __launch_bounds__(256) gemm128_k(const float* __restrict__ A,
        const float* __restrict__ Bw, int K)
{
    __shared__ __align__(16) union {
        struct { float As[2][16*GS]; float Bs[2][16*GS]; } s;
        float Ts[64*129];
    } u;

    int tid = threadIdx.x;
    int tx = tid & 15, ty = tid >> 4;
    int n0 = blockIdx.x * 128;
    int m0 = blockIdx.y * 128;

    int am  = tid >> 1;          // 0..127
    int akq = (tid & 1) * 8;     // 0 or 8
    const float* aP = A  + (size_t)(m0 + am) * K + akq;
    const float* bP = Bw + (size_t)(n0 + am) * K + akq;

    float acc[8][8];
    #pragma unroll
    for (int i = 0; i < 8; i++)
        #pragma unroll
        for (int j = 0; j < 8; j++) acc[i][j] = 0.f;

    float4 ar0 = *(const float4*)(aP);
    float4 ar1 = *(const float4*)(aP + 4);
    float4 br0 = *(const float4*)(bP);
    float4 br1 = *(const float4*)(bP + 4);

    int buf = 0;
    {
        float* As = u.s.As[0]; float* Bs = u.s.Bs[0];
        As[(akq+0)*GS+am]=ar0.x; As[(akq+1)*GS+am]=ar0.y;
        As[(akq+2)*GS+am]=ar0.z; As[(akq+3)*GS+am]=ar0.w;
        As[(akq+4)*GS+am]=ar1.x; As[(akq+5)*GS+am]=ar1.y;
        As[(akq+6)*GS+am]=ar1.z; As[(akq+7)*GS+am]=ar1.w;
        Bs[(akq+0)*GS+am]=br0.x; Bs[(akq+1)*GS+am]=br0.y;
        Bs[(akq+2)*GS+am]=br0.z; Bs[(akq+3)*GS+am]=br0.w;
        Bs[(akq+4)*GS+am]=br1.x; Bs[(akq+5)*GS+am]=br1.y;
        Bs[(akq+6)*GS+am]=br1.z; Bs[(akq+7)*GS+am]=br1.w;
    }
    __syncthreads();

    int nch = K / 16;
    for (int c = 0; c < nch; c++) {
        if (c + 1 < nch) {
            ar0 = *(const float4*)(aP + (c+1)*16);
            ar1 = *(const float4*)(aP + (c+1)*16 + 4);
            br0 = *(const float4*)(bP + (c+1)*16);
            br1 = *(const float4*)(bP + (c+1)*16 + 4);
        }
        const float* As = u.s.As[buf];
        const float* Bs = u.s.Bs[buf];
        #pragma unroll
        for (int kk = 0; kk < 16; kk++) {
            float4 a0 = *(const float4*)&As[kk*GS + ty*8];
            float4 a1 = *(const float4*)&As[kk*GS + ty*8 + 4];
            float4 b0 = *(const float4*)&Bs[kk*GS + tx*8];
            float4 b1 = *(const float4*)&Bs[kk*GS + tx*8 + 4];
            float ar[8] = {a0.x,a0.y,a0.z,a0.w,a1.x,a1.y,a1.z,a1.w};
            float br[8] = {b0.x,b0.y,b0.z,b0.w,b1.x,b1.y,b1.z,b1.w};
            #pragma unroll
            for (int i = 0; i < 8; i++)
                #pragma unroll
                for (int j = 0; j < 8; j++)
                    acc[i][j] = fmaf(ar[i], br[j], acc[i][j]);
        }
        if (c + 1 < nch) {
            __syncthreads();
            float* Asw = u.s.As[buf^1]; float* Bsw = u.s.Bs[buf^1];
            Asw[(akq+0)*GS+am]=ar0.x; Asw[(akq+1)*GS+am]=ar0.y;
            Asw[(akq+2)*GS+am]=ar0.z; Asw[(akq+3)*GS+am]=ar0.w;
            Asw[(akq+4)*GS+am]=ar1.x; Asw[(akq+5)*GS+am]=ar1.y;
            Asw[(akq+6)*GS+am]=ar1.z; Asw[(akq+7)*GS+am]=ar1.w;
            Bsw[(akq+0)*GS+am]=br0.x; Bsw[(akq+1)*GS+am]=br0.y;
            Bsw[(akq+2)*GS+am]=br0.z; Bsw[(akq+3)*GS+am]=br0.w;
            Bsw[(akq+4)*GS+am]=br1.x; Bsw[(akq+5)*GS+am]=br1.y;
            Bsw[(akq+6)*GS+am]=br1.z; Bsw[(akq+7)*GS+am]=br1.w;
            __syncthreads();
            buf ^= 1;
        }
    }

    bool transp = (MODE == 1) || (MODE == 0 && n0 < DI);
    if (transp) {
        int b = m0 >> 12, l0 = m0 & 4095;
        float* dst = (MODE == 0) ? g_xa_pre : g_c_pre;
        #pragma unroll
        for (int h = 0; h < 2; h++) {
            __syncthreads();
            if ((tx >> 3) == h) {
                int txl = tx & 7;
                #pragma unroll
                for (int i = 0; i < 8; i++)
                    #pragma unroll
                    for (int j = 0; j < 8; j++)
                        u.Ts[(txl*8+j)*129 + ty*8+i] = acc[i][j];
            }
            __syncthreads();
            for (int e = tid; e < 64*128; e += 256) {
                int row = e >> 7, cc = e & 127;
                dst[((size_t)(b*DI + n0 + h*64 + row))*LL + l0 + cc] = u.Ts[row*129 + cc];
            }
        }
    } else {
        // MODE 0 z-half: silu, row-major
        #pragma unroll
        for (int i = 0; i < 8; i++) {
            int m = m0 + ty*8 + i;
            #pragma unroll
            for (int j = 0; j < 8; j++) {
                int nz = n0 - DI + tx*8 + j;
                g_z[(size_t)m*DI + nz] = silu_f(acc[i][j]);
            }
        }
    }
}

// =======================================================================
// gemm_k (64-wide, 8x4 micro): used only for the output GEMM (MODE 2)
// =======================================================================
#define AS_STRIDE 132
#define BS_STRIDE 68

__global__ void __launch_bounds__(256) gemm_out_k(const float* __restrict__ Bw,
        int K, float* __restrict__ out, int N)
{
    __shared__ __align__(16) float As[2][16*AS_STRIDE];
    __shared__ __align__(16) float Bs[2][16*BS_STRIDE];

    int tid = threadIdx.x;
    int tx = tid & 15, ty = tid >> 4;
    int n0 = blockIdx.x * 64;
    int m0 = blockIdx.y * 128;
    const float* Ap = g_yz;

    int am  = tid >> 1;
    int akq = (tid & 1) * 8;
    int bn  = tid >> 2;
    int bkq = (tid & 3) * 4;
    const float* aP = Ap + (size_t)(m0 + am) * K + akq;
    const float* bP = Bw + (size_t)(n0 + bn) * K + bkq;

    float acc[8][4];
    #pragma unroll
    for (int i = 0; i < 8; i++)
        #pragma unroll
        for (int j = 0; j < 4; j++) acc[i][j] = 0.f;

    float4 ar0 = *(const float4*)(aP);
    float4 ar1 = *(const float4*)(aP + 4);
    float4 br0 = *(const float4*)(bP);

    int buf = 0;
    {
        As[0][(akq+0)*AS_STRIDE+am]=ar0.x; As[0][(akq+1)*AS_STRIDE+am]=ar0.y;
        As[0][(akq+2)*AS_STRIDE+am]=ar0.z; As[0][(akq+3)*AS_STRIDE+am]=ar0.w;
        As[0][(akq+4)*AS_STRIDE+am]=ar1.x; As[0][(akq+5)*AS_STRIDE+am]=ar1.y;
        As[0][(akq+6)*AS_STRIDE+am]=ar1.z; As[0][(akq+7)*AS_STRIDE+am]=ar1.w;
        Bs[0][(bkq+0)*BS_STRIDE+bn]=br0.x; Bs[0][(bkq+1)*BS_STRIDE+bn]=br0.y;
        Bs[0][(bkq+2)*BS_STRIDE+bn]=br0.z; Bs[0][(bkq+3)*BS_STRIDE+bn]=br0.w;
    }
    __syncthreads();

    int nch = K / 16;
    for (int c = 0; c < nch; c++) {
        if (c + 1 < nch) {
            ar0 = *(const float4*)(aP + (c+1)*16);
            ar1 = *(const float4*)(aP + (c+1)*16 + 4);
            br0 = *(const float4*)(bP + (c+1)*16);
        }
        const float* Asr = As[buf];
        const float* Bsr = Bs[buf];
        #pragma unroll
        for (int kk = 0; kk < 16; kk++) {
            float4 a0 = *(const float4*)&Asr[kk*AS_STRIDE + ty*8];
            float4 a1 = *(const float4*)&Asr[kk*AS_STRIDE + ty*8 + 4];
            float4 b0 = *(const float4*)&Bsr[kk*BS_STRIDE + tx*4];
            float ar[8] = {a0.x,a0.y,a0.z,a0.w,a1.x,a1.y,a1.z,a1.w};
            float br[4] = {b0.x,b0.y,b0.z,b0.w};
            #pragma unroll
            for (int i = 0; i < 8; i++)
                #pragma unroll
                for (int j = 0; j < 4; j++)
                    acc[i][j] = fmaf(ar[i], br[j], acc[i][j]);
        }
        if (c + 1 < nch) {
            __syncthreads();
            float* Asw = As[buf^1]; float* Bsw = Bs[buf^1];
            Asw[(akq+0)*AS_STRIDE+am]=ar0.x; Asw[(akq+1)*AS_STRIDE+am]=ar0.y;
            Asw[(akq+2)*AS_STRIDE+am]=ar0.z; Asw[(akq+3)*AS_STRIDE+am]=ar0.w;
            Asw[(akq+4)*AS_STRIDE+am]=ar1.x; Asw[(akq+5)*AS_STRIDE+am]=ar1.y;
            Asw[(akq+6)*AS_STRIDE+am]=ar1.z; Asw[(akq+7)*AS_STRIDE+am]=ar1.w;
            Bsw[(bkq+0)*BS_STRIDE+bn]=br0.x; Bsw[(bkq+1)*BS_STRIDE+bn]=br0.y;
            Bsw[(bkq+2)*BS_STRIDE+bn]=br0.z; Bsw[(bkq+3)*BS_STRIDE+bn]=br0.w;
            __syncthreads();
            buf ^= 1;
        }
    }

    #pragma unroll
    for (int i = 0; i < 8; i++) {
        int m = m0 + ty*8 + i;
        #pragma unroll
        for (int j = 0; j < 4; j++) {
            int n = n0 + tx*4 + j;
            out[(size_t)m*N + n] = acc[i][j];
        }
    }
}

// =======================================================================
// depthwise conv 3x3 SAME + bias + silu, one (tensor,b,d) image per block
// =======================================================================
__global__ void __launch_bounds__(256) dwconv_k(const float* __restrict__ conv_w,
        const float* __restrict__ conv_b, const float* __restrict__ con_w,
        const float* __restrict__ con_b)
{
    __shared__ __align__(16) float img[LL];
    int blk = blockIdx.x;
    int t  = blk >= BB*DI;
    int bd = t ? blk - BB*DI : blk;
    int d  = bd % DI;
    const float* in  = (t ? g_c_pre : g_xa_pre) + (size_t)bd * LL;
    float*       oup = (t ? g_c_conv : g_xa_conv) + (size_t)bd * LL;
    const float* wp  = (t ? con_w : conv_w) + d * 9;
    float bias = (t ? con_b : conv_b)[d];

    #pragma unroll
    for (int i = 0; i < 4; i++)
        *(float4*)&img[(threadIdx.x + 256*i)*4] = *(const float4*)&in[(threadIdx.x + 256*i)*4];
    float w0=wp[0],w1=wp[1],w2=wp[2],w3=wp[3],w4=wp[4],w5=wp[5],w6=wp[6],w7=wp[7],w8=wp[8];
    __syncthreads();

    #pragma unroll
    for (int i = 0; i < 16; i++) {
        int l = threadIdx.x + 256*i;
        int y = l >> 6, x = l & 63;
        float acc = bias;
        bool yl = y > 0, yh = y < 63, xl = x > 0, xh = x < 63;
        if (yl) {
            if (xl) acc = fmaf(img[l-65], w0, acc);
            acc = fmaf(img[l-64], w1, acc);
            if (xh) acc = fmaf(img[l-63], w2, acc);
        }
        if (xl) acc = fmaf(img[l-1], w3, acc);
        acc = fmaf(img[l], w4, acc);
        if (xh) acc = fmaf(img[l+1], w5, acc);
        if (yh) {
            if (xl) acc = fmaf(img[l+63], w6, acc);
            acc = fmaf(img[l+64], w7, acc);
            if (xh) acc = fmaf(img[l+65], w8, acc);
        }
        oup[l] = silu_f(acc);
    }
}

// =======================================================================
// proj v3: block = 32 pixels, 256 thr, grid = 256 blocks.
// Stage 1: register-blocked GEMM [32x48] = [32x384]x[384x48] (x_proj).
// Stage 2: dt_proj + softplus + scatter (delta,u) / (B,C) to scan order.
// =======================================================================
__global__ void __launch_bounds__(256) proj_k(const float* __restrict__ x_proj_w,
        const float* __restrict__ dt_proj_w, const float* __restrict__ dt_proj_b,
        const int* __restrict__ rev_scan)
{
    __shared__ float sDT[DI*13];
    __shared__ float sDTB[DI];
    __shared__ float xd[32*49];
    __shared__ __align__(16) union {
        struct { float sS[16*36]; float sB[16*48]; } a;
        float xaT[32*33];
    } u;

    int tid = threadIdx.x;
    int b   = blockIdx.x >> 7;
    int l0  = (blockIdx.x & 127) * 32;

    for (int e = tid; e < DI*DR; e += 256)
        sDT[(e/DR)*13 + (e%DR)] = dt_proj_w[e];
    if (tid < 128) {
        sDTB[tid]     = dt_proj_b[tid];
        sDTB[tid+128] = dt_proj_b[tid+128];
        sDTB[tid+256] = dt_proj_b[tid+256];
    }

    int tm = tid & 15, tn = tid >> 4;
    float acc[2][3];
    #pragma unroll
    for (int i = 0; i < 2; i++)
        #pragma unroll
        for (int j = 0; j < 3; j++) acc[i][j] = 0.f;

    // ---- stage 1: x_proj GEMM over K=384 in chunks of 16 ----
    for (int kc = 0; kc < DI/16; kc++) {
        __syncthreads();
        {
            int e0 = tid, e1 = tid + 256;
            int k0 = e0 >> 5, px0 = e0 & 31;
            int k1 = e1 >> 5, px1 = e1 & 31;
            size_t o0 = ((size_t)(b*DI + kc*16 + k0))*LL + l0 + px0;
            size_t o1 = ((size_t)(b*DI + kc*16 + k1))*LL + l0 + px1;
            u.a.sS[k0*36 + px0] = g_xa_conv[o0] + g_c_conv[o0];
            u.a.sS[k1*36 + px1] = g_xa_conv[o1] + g_c_conv[o1];
        }
        #pragma unroll
        for (int i = 0; i < 3; i++) {
            int e = tid + 256*i;
            int cc = e >> 4, kk = e & 15;
            u.a.sB[kk*48 + cc] = (cc < DR + 2*DS)
                ? __ldg(&x_proj_w[(size_t)cc*DI + kc*16 + kk]) : 0.f;
        }
        __syncthreads();
        #pragma unroll
        for (int k = 0; k < 16; k++) {
            float a0 = u.a.sS[k*36 + tm*2];
            float a1 = u.a.sS[k*36 + tm*2 + 1];
            float b0 = u.a.sB[k*48 + tn*3 + 0];
            float b1 = u.a.sB[k*48 + tn*3 + 1];
            float b2 = u.a.sB[k*48 + tn*3 + 2];
            acc[0][0] = fmaf(a0, b0, acc[0][0]);
            acc[0][1] = fmaf(a0, b1, acc[0][1]);
            acc[0][2] = fmaf(a0, b2, acc[0][2]);
            acc[1][0] = fmaf(a1, b0, acc[1][0]);
            acc[1][1] = fmaf(a1, b1, acc[1][1]);
            acc[1][2] = fmaf(a1, b2, acc[1][2]);
        }
    }
    #pragma unroll
    for (int i = 0; i < 2; i++)
        #pragma unroll
        for (int j = 0; j < 3; j++)
            xd[(tm*2+i)*49 + tn*3+j] = acc[i][j];
    __syncthreads();

    int w = tid >> 5, lane = tid & 31;

    // ---- B/C scatter: 32 px x 16 states ----
    #pragma unroll
    for (int p = 0; p < 2; p++) {
        int px = w*4 + p*2 + (lane >> 4);
        int n  = lane & 15;
        int j  = __ldg(&rev_scan[l0 + px]);
        g_bc[((size_t)b*LL + j)*DS + n] =
            make_float2(xd[px*49 + DR + n], xd[px*49 + DR + DS + n]);
    }

    // ---- stage 2: delta + u scatter, 32-d chunks ----
    for (int c32 = 0; c32 < DI/32; c32++) {
        __syncthreads();
        #pragma unroll
        for (int i = 0; i < 4; i++) {
            int e = tid + 256*i;
            int dd = e >> 5, px = e & 31;
            u.xaT[dd*33 + px] =
                g_xa_conv[((size_t)(b*DI + c32*32 + dd))*LL + l0 + px];
        }
        __syncthreads();
        int d = c32*32 + lane;
        float wr[DR];
        #pragma unroll
        for (int r = 0; r < DR; r++) wr[r] = sDT[d*13 + r];
        float bias = sDTB[d];
        #pragma unroll
        for (int p = 0; p < 4; p++) {
            int px = p*8 + w;
            float a = bias;
            #pragma unroll
            for (int r = 0; r < DR; r++) a = fmaf(wr[r], xd[px*49 + r], a);
            float delta = (a > 20.f) ? a : log1pf(__expf(a));
            float uval  = u.xaT[lane*33 + px];
            int j = __ldg(&rev_scan[l0 + px]);
            g_du[((size_t)b*LL + j)*DI + d] = make_float2(delta, uval);
        }
    }
}

// =======================================================================
// selective scan: block = 8 channels of one batch, 128 thr
// =======================================================================
#define TSTEP 32
#define NTILE (LL/TSTEP)   // 128

__global__ void __launch_bounds__(128) scan_k(const float* __restrict__ A_logs,
        const float* __restrict__ Ds, const int* __restrict__ scan_path)
{
    __shared__ __align__(16) float2 du2[2][TSTEP][8];
    __shared__ __align__(16) float2 bc2[2][TSTEP][DS];
    __shared__ float  ps[TSTEP*8*17];
    __shared__ float  s_D[8];

    int tid = threadIdx.x;
    int b   = blockIdx.x / 48;
    int d0  = (blockIdx.x % 48) * 8;
    int wid = tid >> 5, lane = tid & 31;
    int g = lane >> 4, n = lane & 15;
    int ch = wid*2 + g;
    int d = d0 + ch;

    float a_coef = -__expf(A_logs[d*DS + n]);
    if (tid < 8) s_D[tid] = Ds[d0 + tid];

    unsigned du_sm = (unsigned)__cvta_generic_to_shared(&du2[0][0][0]);
    unsigned bc_sm = (unsigned)__cvta_generic_to_shared(&bc2[0][0][0]);
    const float2* du_g = g_du + (size_t)b*LL*DI + d0;
    const float2* bc_g = g_bc + (size_t)b*LL*DS;

    {
        #pragma unroll
        for (int i = 0; i < 2; i++) {
            int e = tid + 128*i;
            int jj = e >> 3, c = e & 7;
            cpa8(du_sm + (unsigned)((jj*8 + c)*8), du_g + (size_t)jj*DI + c);
        }
        #pragma unroll
        for (int i = 0; i < 2; i++) {
            int e = tid + 128*i;
            int jj = e >> 3, q = e & 7;
            cpa16(bc_sm + (unsigned)((jj*DS + q*2)*8), bc_g + (size_t)jj*DS + q*2);
        }
        cp_commit();
    }

    float h = 0.f;
    int buf = 0;
    for (int T = 0; T < NTILE; T++) {
        if (T + 1 < NTILE) {
            int o = (buf^1) * TSTEP;
            #pragma unroll
            for (int i = 0; i < 2; i++) {
                int e = tid + 128*i;
                int jj = e >> 3, c = e & 7;
                cpa8(du_sm + (unsigned)(((o+jj)*8 + c)*8),
                     du_g + (size_t)((T+1)*TSTEP + jj)*DI + c);
            }
            #pragma unroll
            for (int i = 0; i < 2; i++) {
                int e = tid + 128*i;
                int jj = e >> 3, q = e & 7;
                cpa16(bc_sm + (unsigned)(((o+jj)*DS + q*2)*8),
                      bc_g + (size_t)((T+1)*TSTEP + jj)*DS + q*2);
            }
            cp_commit();
            cp_wait1();
        } else {
            cp_wait0();
        }
        __syncthreads();

        #pragma unroll 8
        for (int jj = 0; jj < TSTEP; jj++) {
            float2 du = du2[buf][jj][ch];
            float2 bc = bc2[buf][jj][n];
            float dA = __expf(du.x * a_coef);
            h = fmaf(dA, h, du.x * du.y * bc.x);
            ps[(jj*8 + ch)*17 + n] = h * bc.y;
        }
        __syncthreads();

        #pragma unroll
        for (int i = 0; i < 2; i++) {
            int e = tid + 128*i;
            int jj = e >> 3, c = e & 7;
            const float* p = &ps[(jj*8 + c)*17];
            float sum = p[0];
            #pragma unroll
            for (int k = 1; k < DS; k++) sum += p[k];
            float uval = du2[buf][jj][c].y;
            int pos = __ldg(&scan_path[T*TSTEP + jj]);
            g_y[((size_t)b*LL + pos)*DI + d0 + c] = fmaf(uval, s_D[c], sum);
        }
        buf ^= 1;
    }
}

// =======================================================================
// layernorm over d + multiply by silu(z)
// =======================================================================
__global__ void __launch_bounds__(128) ln_mul_k(const float* __restrict__ ln_w,
                                                const float* __restrict__ ln_b)
{
    int row = blockIdx.x;
    const float* yr = g_y + (size_t)row * DI;
    float v0 = yr[threadIdx.x], v1 = yr[threadIdx.x + 128], v2 = yr[threadIdx.x + 256];
    float s = v0 + v1 + v2;
    float q = v0*v0 + v1*v1 + v2*v2;
    #pragma unroll
    for (int o = 16; o > 0; o >>= 1) {
        s += __shfl_xor_sync(0xFFFFFFFFu, s, o);
        q += __shfl_xor_sync(0xFFFFFFFFu, q, o);
    }
    __shared__ float ss[4], sq[4];
    int w = threadIdx.x >> 5, lane = threadIdx.x & 31;
    if (lane == 0) { ss[w] = s; sq[w] = q; }
    __syncthreads();
    s = ss[0] + ss[1] + ss[2] + ss[3];
    q = sq[0] + sq[1] + sq[2] + sq[3];
    float mean = s * (1.f / DI);
    float var  = q * (1.f / DI) - mean * mean;
    float rstd = rsqrtf(var + 1e-5f);
    const float* zr = g_z + (size_t)row * DI;
    float* o = g_yz + (size_t)row * DI;
    float vv[3] = {v0, v1, v2};
    #pragma unroll
    for (int i = 0; i < 3; i++) {
        int dd = threadIdx.x + i * 128;
        o[dd] = ((vv[i] - mean) * rstd * ln_w[dd] + ln_b[dd]) * zr[dd];
    }
}

// ---------------- launch ----------------
extern "C" void kernel_launch(void* const* d_in, const int* in_sizes, int n_in,
                              void* d_out, int out_size)
{
    const float* x          = (const float*)d_in[0];
    const float* cond       = (const float*)d_in[1];
    const float* W_in       = (const float*)d_in[2];
    const float* W_con      = (const float*)d_in[3];
    const float* conv_w     = (const float*)d_in[4];
    const float* conv_b     = (const float*)d_in[5];
    const float* con_conv_w = (const float*)d_in[6];
    const float* con_conv_b = (const float*)d_in[7];
    const float* x_proj_w   = (const float*)d_in[8];
    const float* dt_proj_w  = (const float*)d_in[9];
    const float* dt_proj_b  = (const float*)d_in[10];
    const float* A_logs     = (const float*)d_in[11];
    const float* Ds         = (const float*)d_in[12];
    const float* ln_w       = (const float*)d_in[13];
    const float* ln_b       = (const float*)d_in[14];
    const float* W_out      = (const float*)d_in[15];
    const int*   scan_path  = (const int*)d_in[16];
    const int*   rev_scan   = (const int*)d_in[17];
    float* out = (float*)d_out;

    gemm128_k<0><<<dim3(2*DI/128, NROWS/128), 256>>>(x,    W_in,  DM);
    gemm128_k<1><<<dim3(DI/128,   NROWS/128), 256>>>(cond, W_con, DM);
    dwconv_k<<<2*BB*DI, 256>>>(conv_w, conv_b, con_conv_w, con_conv_b);
    proj_k<<<NROWS/32, 256>>>(x_proj_w, dt_proj_w, dt_proj_b, rev_scan);
    scan_k<<<(BB*DI)/8, 128>>>(A_logs, Ds, scan_path);
    ln_mul_k<<<NROWS, 128>>>(ln_w, ln_b);
    gemm_out_k<<<dim3(DM/64, NROWS/128), 256>>>(W_out, DI, out, DM);
}

// round 6
// speedup vs baseline: 1.0707x; 1.0707x over previous
#include <cuda_runtime.h>

#define BB 2
#define DM 192
#define DI 384
#define DS 16
#define DR 12
#define HH 64
#define WW 64
#define LL 4096
#define NROWS (BB*LL)   // 8192

// ---------------- scratch ----------------
__device__ float  g_xa_pre[BB*DI*LL];   // xz first half, NCHW
__device__ float  g_c_pre [BB*DI*LL];
__device__ float  g_xa_conv[BB*DI*LL];  // silu(dwconv(xa))
__device__ float  g_s     [BB*DI*LL];   // silu(dwconv(xa)) + silu(dwconv(c))
__device__ float  g_z     [NROWS*DI];   // silu(z), (b*l, d)
__device__ float2 g_du    [BB*LL*DI];   // (delta, u) in scan order [b][j][d]
__device__ float2 g_bc    [BB*LL*DS];   // (B_n, C_n) in scan order [b][j][n]
__device__ float  g_y     [NROWS*DI];   // scan output, spatial order, (b*l, d)
__device__ float  g_yz    [NROWS*DI];

__device__ __forceinline__ float silu_f(float v){ return v / (1.f + __expf(-v)); }

__device__ __forceinline__ void cpa4(unsigned dst, const void* src){
    asm volatile("cp.async.ca.shared.global [%0], [%1], 4;\n" :: "r"(dst), "l"(src));
}
__device__ __forceinline__ void cpa8(unsigned dst, const void* src){
    asm volatile("cp.async.ca.shared.global [%0], [%1], 8;\n" :: "r"(dst), "l"(src));
}
__device__ __forceinline__ void cpa16(unsigned dst, const void* src){
    asm volatile("cp.async.ca.shared.global [%0], [%1], 16;\n" :: "r"(dst), "l"(src));
}
__device__ __forceinline__ void cp_commit(){ asm volatile("cp.async.commit_group;\n"); }
__device__ __forceinline__ void cp_wait1(){ asm volatile("cp.async.wait_group 1;\n"); }
__device__ __forceinline__ void cp_wait0(){ asm volatile("cp.async.wait_group 0;\n"); }

// =======================================================================
// GEMM: C[M,N] = A[M,K] * B[N,K]^T.  128x64 tile, 256 thr, 8x4 micro.
// MODE 0: xz (n<DI -> xa NCHW via transpose; n>=DI -> silu(z) row-major)
// MODE 1: cond -> NCHW via transpose
// MODE 2: plain store to out
// =======================================================================
#define AS_STRIDE 132   // % 4 == 0 (16B-aligned float4 rows)
#define BS_STRIDE 68    // % 4 == 0 (16B-aligned float4 rows)

template<int MODE>
__global__ void __launch_bounds__(256) gemm_k(const float* __restrict__ A,
        const float* __restrict__ Bw, int M, int N, int K, float* __restrict__ out)
{
    __shared__ __align__(16) union {
        struct { float As[2][16*AS_STRIDE]; float Bs[2][16*BS_STRIDE]; } s;
        float Ts[64*129];
    } u;

    int tid = threadIdx.x;
    int tx = tid & 15, ty = tid >> 4;
    int n0 = blockIdx.x * 64;
    int m0 = blockIdx.y * 128;
    const float* Ap = (MODE == 2) ? g_yz : A;

    int am  = tid >> 1;          // 0..127
    int akq = (tid & 1) * 8;     // 0 or 8
    int bn  = tid >> 2;          // 0..63
    int bkq = (tid & 3) * 4;     // 0,4,8,12
    const float* aP = Ap + (size_t)(m0 + am) * K + akq;
    const float* bP = Bw + (size_t)(n0 + bn) * K + bkq;

    float acc[8][4];
    #pragma unroll
    for (int i = 0; i < 8; i++)
        #pragma unroll
        for (int j = 0; j < 4; j++) acc[i][j] = 0.f;

    float4 ar0 = *(const float4*)(aP);
    float4 ar1 = *(const float4*)(aP + 4);
    float4 br0 = *(const float4*)(bP);

    int buf = 0;
    {
        float* As = u.s.As[0]; float* Bs = u.s.Bs[0];
        As[(akq+0)*AS_STRIDE+am]=ar0.x; As[(akq+1)*AS_STRIDE+am]=ar0.y;
        As[(akq+2)*AS_STRIDE+am]=ar0.z; As[(akq+3)*AS_STRIDE+am]=ar0.w;
        As[(akq+4)*AS_STRIDE+am]=ar1.x; As[(akq+5)*AS_STRIDE+am]=ar1.y;
        As[(akq+6)*AS_STRIDE+am]=ar1.z; As[(akq+7)*AS_STRIDE+am]=ar1.w;
        Bs[(bkq+0)*BS_STRIDE+bn]=br0.x; Bs[(bkq+1)*BS_STRIDE+bn]=br0.y;
        Bs[(bkq+2)*BS_STRIDE+bn]=br0.z; Bs[(bkq+3)*BS_STRIDE+bn]=br0.w;
    }
    __syncthreads();

    int nch = K / 16;
    for (int c = 0; c < nch; c++) {
        if (c + 1 < nch) {
            ar0 = *(const float4*)(aP + (c+1)*16);
            ar1 = *(const float4*)(aP + (c+1)*16 + 4);
            br0 = *(const float4*)(bP + (c+1)*16);
        }
        const float* As = u.s.As[buf];
        const float* Bs = u.s.Bs[buf];
        #pragma unroll
        for (int kk = 0; kk < 16; kk++) {
            float4 a0 = *(const float4*)&As[kk*AS_STRIDE + ty*8];
            float4 a1 = *(const float4*)&As[kk*AS_STRIDE + ty*8 + 4];
            float4 b0 = *(const float4*)&Bs[kk*BS_STRIDE + tx*4];
            float ar[8] = {a0.x,a0.y,a0.z,a0.w,a1.x,a1.y,a1.z,a1.w};
            float br[4] = {b0.x,b0.y,b0.z,b0.w};
            #pragma unroll
            for (int i = 0; i < 8; i++)
                #pragma unroll
                for (int j = 0; j < 4; j++)
                    acc[i][j] = fmaf(ar[i], br[j], acc[i][j]);
        }
        if (c + 1 < nch) {
            __syncthreads();
            float* Asw = u.s.As[buf^1]; float* Bsw = u.s.Bs[buf^1];
            Asw[(akq+0)*AS_STRIDE+am]=ar0.x; Asw[(akq+1)*AS_STRIDE+am]=ar0.y;
            Asw[(akq+2)*AS_STRIDE+am]=ar0.z; Asw[(akq+3)*AS_STRIDE+am]=ar0.w;
            Asw[(akq+4)*AS_STRIDE+am]=ar1.x; Asw[(akq+5)*AS_STRIDE+am]=ar1.y;
            Asw[(akq+6)*AS_STRIDE+am]=ar1.z; Asw[(akq+7)*AS_STRIDE+am]=ar1.w;
            Bsw[(bkq+0)*BS_STRIDE+bn]=br0.x; Bsw[(bkq+1)*BS_STRIDE+bn]=br0.y;
            Bsw[(bkq+2)*BS_STRIDE+bn]=br0.z; Bsw[(bkq+3)*BS_STRIDE+bn]=br0.w;
            __syncthreads();
            buf ^= 1;
        }
    }

    bool transp = (MODE == 0 && n0 < DI) || (MODE == 1);
    if (transp) {
        __syncthreads();
        #pragma unroll
        for (int i = 0; i < 8; i++)
            #pragma unroll
            for (int j = 0; j < 4; j++)
                u.Ts[(tx*4+j)*129 + ty*8+i] = acc[i][j];
        __syncthreads();
        int b = m0 >> 12, l0 = m0 & 4095;
        float* dst = (MODE == 0) ? g_xa_pre : g_c_pre;
        for (int e = tid; e < 64*128; e += 256) {
            int row = e >> 7, cc = e & 127;
            dst[((size_t)(b*DI + n0 + row))*LL + l0 + cc] = u.Ts[row*129 + cc];
        }
    } else {
        #pragma unroll
        for (int i = 0; i < 8; i++) {
            int m = m0 + ty*8 + i;
            #pragma unroll
            for (int j = 0; j < 4; j++) {
                int n = n0 + tx*4 + j;
                float v = acc[i][j];
                if (MODE == 0)      g_z[(size_t)m*DI + (n - DI)] = silu_f(v);
                else if (MODE == 2) out[(size_t)m*N + n] = v;
            }
        }
    }
}

// =======================================================================
// depthwise conv 3x3 SAME + bias + silu for BOTH tensors, one (b,d) per
// block.  Writes g_xa_conv = silu(conv(xa)) and g_s = sum of both silus.
// =======================================================================
__global__ void __launch_bounds__(256) dwconv_k(const float* __restrict__ conv_w,
        const float* __restrict__ conv_b, const float* __restrict__ con_w,
        const float* __restrict__ con_b)
{
    __shared__ __align__(16) float imx[LL];
    __shared__ __align__(16) float imc[LL];
    int bd = blockIdx.x;
    int d  = bd % DI;
    const float* inx = g_xa_pre + (size_t)bd * LL;
    const float* inc = g_c_pre  + (size_t)bd * LL;
    float* outx = g_xa_conv + (size_t)bd * LL;
    float* outs = g_s       + (size_t)bd * LL;
    const float* wxp = conv_w + d * 9;
    const float* wcp = con_w  + d * 9;
    float bx = conv_b[d], bc = con_b[d];

    #pragma unroll
    for (int i = 0; i < 4; i++) {
        *(float4*)&imx[(threadIdx.x + 256*i)*4] = *(const float4*)&inx[(threadIdx.x + 256*i)*4];
        *(float4*)&imc[(threadIdx.x + 256*i)*4] = *(const float4*)&inc[(threadIdx.x + 256*i)*4];
    }
    float wx[9], wc[9];
    #pragma unroll
    for (int i = 0; i < 9; i++) { wx[i] = wxp[i]; wc[i] = wcp[i]; }
    __syncthreads();

    #pragma unroll
    for (int i = 0; i < 16; i++) {
        int l = threadIdx.x + 256*i;
        int y = l >> 6, x = l & 63;
        bool yl = y > 0, yh = y < 63, xl = x > 0, xh = x < 63;
        float ax = bx, ac = bc;
        if (yl) {
            if (xl) { ax = fmaf(imx[l-65], wx[0], ax); ac = fmaf(imc[l-65], wc[0], ac); }
            ax = fmaf(imx[l-64], wx[1], ax); ac = fmaf(imc[l-64], wc[1], ac);
            if (xh) { ax = fmaf(imx[l-63], wx[2], ax); ac = fmaf(imc[l-63], wc[2], ac); }
        }
        if (xl) { ax = fmaf(imx[l-1], wx[3], ax); ac = fmaf(imc[l-1], wc[3], ac); }
        ax = fmaf(imx[l], wx[4], ax); ac = fmaf(imc[l], wc[4], ac);
        if (xh) { ax = fmaf(imx[l+1], wx[5], ax); ac = fmaf(imc[l+1], wc[5], ac); }
        if (yh) {
            if (xl) { ax = fmaf(imx[l+63], wx[6], ax); ac = fmaf(imc[l+63], wc[6], ac); }
            ax = fmaf(imx[l+64], wx[7], ax); ac = fmaf(imc[l+64], wc[7], ac);
            if (xh) { ax = fmaf(imx[l+65], wx[8], ax); ac = fmaf(imc[l+65], wc[8], ac); }
        }
        float sa = silu_f(ax);
        outx[l] = sa;
        outs[l] = sa + silu_f(ac);
    }
}

// =======================================================================
// proj: block = 64 pixels, 256 thr, cp.async double-buffered stage 1.
// Stage 1: [64x48] = [64x384]x[384x48] (x_proj) reading g_s only.
// Stage 2: dt_proj + softplus + scatter (delta,u) / (B,C) to scan order.
// =======================================================================
__global__ void __launch_bounds__(256) proj_k(const float* __restrict__ x_proj_w,
        const float* __restrict__ dt_proj_w, const float* __restrict__ dt_proj_b,
        const int* __restrict__ rev_scan)
{
    __shared__ float sDT[DI*13];
    __shared__ float sDTB[DI];
    __shared__ float xd[64*49];
    __shared__ __align__(16) union {
        struct { float sS[2][16*68]; float sB[2][16*48]; } a;
        float xaT[32*69];
    } u;

    int tid = threadIdx.x;
    int b   = blockIdx.x >> 6;
    int l0  = (blockIdx.x & 63) * 64;

    for (int e = tid; e < DI*DR; e += 256)
        sDT[(e/DR)*13 + (e%DR)] = dt_proj_w[e];
    if (tid < 128) {
        sDTB[tid]     = dt_proj_b[tid];
        sDTB[tid+128] = dt_proj_b[tid+128];
        sDTB[tid+256] = dt_proj_b[tid+256];
    }
    // zero sB (pads at cc>=44 stay zero; cp.async only fills cc<44)
    for (int e = tid; e < 2*16*48; e += 256) (&u.a.sB[0][0])[e] = 0.f;

    unsigned sS_b = (unsigned)__cvta_generic_to_shared(&u.a.sS[0][0]);
    unsigned sB_b = (unsigned)__cvta_generic_to_shared(&u.a.sB[0][0]);

    // prefetch lambda (manual): chunk kc into buffer bf
    #define PROJ_PREFETCH(kc, bf)                                              \
    {                                                                          \
        int k = tid >> 4, px4 = tid & 15;                                      \
        cpa16(sS_b + (unsigned)(((bf)*16*68 + k*68 + px4*4)*4),                \
              g_s + ((size_t)(b*DI + (kc)*16 + k))*LL + l0 + px4*4);           \
        _Pragma("unroll")                                                      \
        for (int i = 0; i < 3; i++) {                                          \
            int e = tid + 256*i;                                               \
            int cc = e >> 4, kk = e & 15;                                      \
            if (cc < DR + 2*DS)                                                \
                cpa4(sB_b + (unsigned)(((bf)*16*48 + kk*48 + cc)*4),           \
                     x_proj_w + (size_t)cc*DI + (kc)*16 + kk);                 \
        }                                                                      \
    }

    int tm = tid & 15, tn = tid >> 4;
    float acc[4][3];
    #pragma unroll
    for (int i = 0; i < 4; i++)
        #pragma unroll
        for (int j = 0; j < 3; j++) acc[i][j] = 0.f;

    PROJ_PREFETCH(0, 0); cp_commit();

    int buf = 0;
    for (int kc = 0; kc < DI/16; kc++) {
        if (kc + 1 < DI/16) { PROJ_PREFETCH(kc+1, buf^1); cp_commit(); cp_wait1(); }
        else                { cp_wait0(); }
        __syncthreads();
        const float* sS = u.a.sS[buf];
        const float* sB = u.a.sB[buf];
        #pragma unroll
        for (int k = 0; k < 16; k++) {
            float4 av = *(const float4*)&sS[k*68 + tm*4];
            float b0 = sB[k*48 + tn*3 + 0];
            float b1 = sB[k*48 + tn*3 + 1];
            float b2 = sB[k*48 + tn*3 + 2];
            float ar[4] = {av.x, av.y, av.z, av.w};
            #pragma unroll
            for (int i = 0; i < 4; i++) {
                acc[i][0] = fmaf(ar[i], b0, acc[i][0]);
                acc[i][1] = fmaf(ar[i], b1, acc[i][1]);
                acc[i][2] = fmaf(ar[i], b2, acc[i][2]);
            }
        }
        __syncthreads();
        buf ^= 1;
    }
    #pragma unroll
    for (int i = 0; i < 4; i++)
        #pragma unroll
        for (int j = 0; j < 3; j++)
            xd[(tm*4+i)*49 + tn*3+j] = acc[i][j];
    __syncthreads();

    int w = tid >> 5, lane = tid & 31;

    // ---- B/C scatter ----
    #pragma unroll
    for (int p = 0; p < 4; p++) {
        int px = w*8 + p*2 + (lane >> 4);
        int n  = lane & 15;
        int j  = __ldg(&rev_scan[l0 + px]);
        g_bc[((size_t)b*LL + j)*DS + n] =
            make_float2(xd[px*49 + DR + n], xd[px*49 + DR + DS + n]);
    }

    // ---- stage 2: delta + u scatter, 32-d chunks ----
    for (int c32 = 0; c32 < DI/32; c32++) {
        __syncthreads();
        #pragma unroll
        for (int i = 0; i < 8; i++) {
            int e = tid + 256*i;
            int dd = e >> 6, px = e & 63;
            u.xaT[dd*69 + px] =
                g_xa_conv[((size_t)(b*DI + c32*32 + dd))*LL + l0 + px];
        }
        __syncthreads();
        int d = c32*32 + lane;
        float wr[DR];
        #pragma unroll
        for (int r = 0; r < DR; r++) wr[r] = sDT[d*13 + r];
        float bias = sDTB[d];
        #pragma unroll
        for (int p = 0; p < 8; p++) {
            int px = p*8 + w;
            float a = bias;
            #pragma unroll
            for (int r = 0; r < DR; r++) a = fmaf(wr[r], xd[px*49 + r], a);
            float delta = (a > 20.f) ? a : log1pf(__expf(a));
            float uval  = u.xaT[lane*69 + px];
            int j = __ldg(&rev_scan[l0 + px]);
            g_du[((size_t)b*LL + j)*DI + d] = make_float2(delta, uval);
        }
    }
}

// =======================================================================
// selective scan: block = 8 channels of one batch, 128 thr
// =======================================================================
#define TSTEP 32
#define NTILE (LL/TSTEP)   // 128

__global__ void __launch_bounds__(128) scan_k(const float* __restrict__ A_logs,
        const float* __restrict__ Ds, const int* __restrict__ scan_path)
{
    __shared__ __align__(16) float2 du2[2][TSTEP][8];
    __shared__ __align__(16) float2 bc2[2][TSTEP][DS];
    __shared__ float  ps[TSTEP*8*17];
    __shared__ float  s_D[8];

    int tid = threadIdx.x;
    int b   = blockIdx.x / 48;
    int d0  = (blockIdx.x % 48) * 8;
    int wid = tid >> 5, lane = tid & 31;
    int g = lane >> 4, n = lane & 15;
    int ch = wid*2 + g;
    int d = d0 + ch;

    float a_coef = -__expf(A_logs[d*DS + n]);
    if (tid < 8) s_D[tid] = Ds[d0 + tid];

    unsigned du_sm = (unsigned)__cvta_generic_to_shared(&du2[0][0][0]);
    unsigned bc_sm = (unsigned)__cvta_generic_to_shared(&bc2[0][0][0]);
    const float2* du_g = g_du + (size_t)b*LL*DI + d0;
    const float2* bc_g = g_bc + (size_t)b*LL*DS;

    {
        #pragma unroll
        for (int i = 0; i < 2; i++) {
            int e = tid + 128*i;
            int jj = e >> 3, c = e & 7;
            cpa8(du_sm + (unsigned)((jj*8 + c)*8), du_g + (size_t)jj*DI + c);
        }
        #pragma unroll
        for (int i = 0; i < 2; i++) {
            int e = tid + 128*i;
            int jj = e >> 3, q = e & 7;
            cpa16(bc_sm + (unsigned)((jj*DS + q*2)*8), bc_g + (size_t)jj*DS + q*2);
        }
        cp_commit();
    }

    float h = 0.f;
    int buf = 0;
    for (int T = 0; T < NTILE; T++) {
        if (T + 1 < NTILE) {
            int o = (buf^1) * TSTEP;
            #pragma unroll
            for (int i = 0; i < 2; i++) {
                int e = tid + 128*i;
                int jj = e >> 3, c = e & 7;
                cpa8(du_sm + (unsigned)(((o+jj)*8 + c)*8),
                     du_g + (size_t)((T+1)*TSTEP + jj)*DI + c);
            }
            #pragma unroll
            for (int i = 0; i < 2; i++) {
                int e = tid + 128*i;
                int jj = e >> 3, q = e & 7;
                cpa16(bc_sm + (unsigned)(((o+jj)*DS + q*2)*8),
                      bc_g + (size_t)((T+1)*TSTEP + jj)*DS + q*2);
            }
            cp_commit();
            cp_wait1();
        } else {
            cp_wait0();
        }
        __syncthreads();

        #pragma unroll 8
        for (int jj = 0; jj < TSTEP; jj++) {
            float2 du = du2[buf][jj][ch];
            float2 bc = bc2[buf][jj][n];
            float dA = __expf(du.x * a_coef);
            h = fmaf(dA, h, du.x * du.y * bc.x);
            ps[(jj*8 + ch)*17 + n] = h * bc.y;
        }
        __syncthreads();

        #pragma unroll
        for (int i = 0; i < 2; i++) {
            int e = tid + 128*i;
            int jj = e >> 3, c = e & 7;
            const float* p = &ps[(jj*8 + c)*17];
            float sum = p[0];
            #pragma unroll
            for (int k = 1; k < DS; k++) sum += p[k];
            float uval = du2[buf][jj][c].y;
            int pos = __ldg(&scan_path[T*TSTEP + jj]);
            g_y[((size_t)b*LL + pos)*DI + d0 + c] = fmaf(uval, s_D[c], sum);
        }
        buf ^= 1;
    }
}

// =======================================================================
// layernorm over d + multiply by silu(z)
// =======================================================================
__global__ void __launch_bounds__(128) ln_mul_k(const float* __restrict__ ln_w,
                                                const float* __restrict__ ln_b)
{
    int row = blockIdx.x;
    const float* yr = g_y + (size_t)row * DI;
    float v0 = yr[threadIdx.x], v1 = yr[threadIdx.x + 128], v2 = yr[threadIdx.x + 256];
    float s = v0 + v1 + v2;
    float q = v0*v0 + v1*v1 + v2*v2;
    #pragma unroll
    for (int o = 16; o > 0; o >>= 1) {
        s += __shfl_xor_sync(0xFFFFFFFFu, s, o);
        q += __shfl_xor_sync(0xFFFFFFFFu, q, o);
    }
    __shared__ float ss[4], sq[4];
    int w = threadIdx.x >> 5, lane = threadIdx.x & 31;
    if (lane == 0) { ss[w] = s; sq[w] = q; }
    __syncthreads();
    s = ss[0] + ss[1] + ss[2] + ss[3];
    q = sq[0] + sq[1] + sq[2] + sq[3];
    float mean = s * (1.f / DI);
    float var  = q * (1.f / DI) - mean * mean;
    float rstd = rsqrtf(var + 1e-5f);
    const float* zr = g_z + (size_t)row * DI;
    float* o = g_yz + (size_t)row * DI;
    float vv[3] = {v0, v1, v2};
    #pragma unroll
    for (int i = 0; i < 3; i++) {
        int dd = threadIdx.x + i * 128;
        o[dd] = ((vv[i] - mean) * rstd * ln_w[dd] + ln_b[dd]) * zr[dd];
    }
}

// ---------------- launch ----------------
extern "C" void kernel_launch(void* const* d_in, const int* in_sizes, int n_in,
                              void* d_out, int out_size)
{
    const float* x          = (const float*)d_in[0];
    const float* cond       = (const float*)d_in[1];
    const float* W_in       = (const float*)d_in[2];
    const float* W_con      = (const float*)d_in[3];
    const float* conv_w     = (const float*)d_in[4];
    const float* conv_b     = (const float*)d_in[5];
    const float* con_conv_w = (const float*)d_in[6];
    const float* con_conv_b = (const float*)d_in[7];
    const float* x_proj_w   = (const float*)d_in[8];
    const float* dt_proj_w  = (const float*)d_in[9];
    const float* dt_proj_b  = (const float*)d_in[10];
    const float* A_logs     = (const float*)d_in[11];
    const float* Ds         = (const float*)d_in[12];
    const float* ln_w       = (const float*)d_in[13];
    const float* ln_b       = (const float*)d_in[14];
    const float* W_out      = (const float*)d_in[15];
    const int*   scan_path  = (const int*)d_in[16];
    const int*   rev_scan   = (const int*)d_in[17];
    float* out = (float*)d_out;

    gemm_k<0><<<dim3(2*DI/64, NROWS/128), 256>>>(x,    W_in,  NROWS, 2*DI, DM, nullptr);
    gemm_k<1><<<dim3(DI/64,   NROWS/128), 256>>>(cond, W_con, NROWS, DI,   DM, nullptr);
    dwconv_k<<<BB*DI, 256>>>(conv_w, conv_b, con_conv_w, con_conv_b);
    proj_k<<<NROWS/64, 256>>>(x_proj_w, dt_proj_w, dt_proj_b, rev_scan);
    scan_k<<<(BB*DI)/8, 128>>>(A_logs, Ds, scan_path);
    ln_mul_k<<<NROWS, 128>>>(ln_w, ln_b);
    gemm_k<2><<<dim3(DM/64, NROWS/128), 256>>>(nullptr, W_out, NROWS, DM, DI, out);
}

// round 7
// speedup vs baseline: 1.1244x; 1.0501x over previous
#include <cuda_runtime.h>

#define BB 2
#define DM 192
#define DI 384
#define DS 16
#define DR 12
#define HH 64
#define WW 64
#define LL 4096
#define NROWS (BB*LL)   // 8192

// ---------------- scratch ----------------
__device__ float  g_xa_pre[BB*DI*LL];   // xz first half, NCHW
__device__ float  g_c_pre [BB*DI*LL];
__device__ float  g_xa_conv[BB*DI*LL];  // silu(dwconv(xa))
__device__ float  g_s     [BB*DI*LL];   // silu(dwconv(xa)) + silu(dwconv(c))
__device__ float  g_z     [NROWS*DI];   // silu(z), (b*l, d)
__device__ float2 g_du    [BB*LL*DI];   // (delta, u) in scan order [b][j][d]
__device__ float2 g_bc    [BB*LL*DS];   // (B_n, C_n) in scan order [b][j][n]
__device__ float  g_y     [NROWS*DI];   // scan output, spatial order, (b*l, d)
__device__ float2 g_stats [NROWS];      // (mu, rstd) per row

__device__ __forceinline__ float silu_f(float v){ return v / (1.f + __expf(-v)); }

__device__ __forceinline__ void cpa4(unsigned dst, const void* src){
    asm volatile("cp.async.ca.shared.global [%0], [%1], 4;\n" :: "r"(dst), "l"(src));
}
__device__ __forceinline__ void cpa8(unsigned dst, const void* src){
    asm volatile("cp.async.ca.shared.global [%0], [%1], 8;\n" :: "r"(dst), "l"(src));
}
__device__ __forceinline__ void cpa16(unsigned dst, const void* src){
    asm volatile("cp.async.ca.shared.global [%0], [%1], 16;\n" :: "r"(dst), "l"(src));
}
__device__ __forceinline__ void cp_commit(){ asm volatile("cp.async.commit_group;\n"); }
__device__ __forceinline__ void cp_wait1(){ asm volatile("cp.async.wait_group 1;\n"); }
__device__ __forceinline__ void cp_wait0(){ asm volatile("cp.async.wait_group 0;\n"); }

#define AS_STRIDE 132
#define BS_STRIDE 68

// =======================================================================
// gemm_in: BOTH input GEMMs in one launch. 128x64 tile, 8x4 micro.
// n0 in [0,384): xa -> NCHW transpose.  [384,768): silu(z) row-major.
// n0 in [768,1152): cond -> NCHW transpose (col n0-768).
// Single __syncthreads per K-chunk.
// =======================================================================
__global__ void __launch_bounds__(256) gemm_in_k(const float* __restrict__ x,
        const float* __restrict__ cond, const float* __restrict__ W_in,
        const float* __restrict__ W_con)
{
    __shared__ __align__(16) union {
        struct { float As[2][16*AS_STRIDE]; float Bs[2][16*BS_STRIDE]; } s;
        float Ts[64*129];
    } u;

    const int K = DM;
    int tid = threadIdx.x;
    int tx = tid & 15, ty = tid >> 4;
    int n0 = blockIdx.x * 64;
    int m0 = blockIdx.y * 128;
    bool is_c = (n0 >= 2*DI);
    const float* A  = is_c ? cond  : x;
    const float* Bw = is_c ? W_con : W_in;
    int nb = is_c ? n0 - 2*DI : n0;

    int am  = tid >> 1;
    int akq = (tid & 1) * 8;
    int bn  = tid >> 2;
    int bkq = (tid & 3) * 4;
    const float* aP = A  + (size_t)(m0 + am) * K + akq;
    const float* bP = Bw + (size_t)(nb + bn) * K + bkq;

    float acc[8][4];
    #pragma unroll
    for (int i = 0; i < 8; i++)
        #pragma unroll
        for (int j = 0; j < 4; j++) acc[i][j] = 0.f;

    // prologue: chunk 0 into buf 0
    {
        float4 a0 = *(const float4*)(aP);
        float4 a1 = *(const float4*)(aP + 4);
        float4 b0 = *(const float4*)(bP);
        float* As = u.s.As[0]; float* Bs = u.s.Bs[0];
        As[(akq+0)*AS_STRIDE+am]=a0.x; As[(akq+1)*AS_STRIDE+am]=a0.y;
        As[(akq+2)*AS_STRIDE+am]=a0.z; As[(akq+3)*AS_STRIDE+am]=a0.w;
        As[(akq+4)*AS_STRIDE+am]=a1.x; As[(akq+5)*AS_STRIDE+am]=a1.y;
        As[(akq+6)*AS_STRIDE+am]=a1.z; As[(akq+7)*AS_STRIDE+am]=a1.w;
        Bs[(bkq+0)*BS_STRIDE+bn]=b0.x; Bs[(bkq+1)*BS_STRIDE+bn]=b0.y;
        Bs[(bkq+2)*BS_STRIDE+bn]=b0.z; Bs[(bkq+3)*BS_STRIDE+bn]=b0.w;
    }

    int buf = 0;
    const int nch = K / 16;   // 12
    for (int c = 0; c < nch; c++) {
        float4 na0, na1, nb0;
        if (c + 1 < nch) {
            na0 = *(const float4*)(aP + (c+1)*16);
            na1 = *(const float4*)(aP + (c+1)*16 + 4);
            nb0 = *(const float4*)(bP + (c+1)*16);
        }
        __syncthreads();
        const float* As = u.s.As[buf];
        const float* Bs = u.s.Bs[buf];
        #pragma unroll
        for (int kk = 0; kk < 16; kk++) {
            float4 a0 = *(const float4*)&As[kk*AS_STRIDE + ty*8];
            float4 a1 = *(const float4*)&As[kk*AS_STRIDE + ty*8 + 4];
            float4 b0 = *(const float4*)&Bs[kk*BS_STRIDE + tx*4];
            float ar[8] = {a0.x,a0.y,a0.z,a0.w,a1.x,a1.y,a1.z,a1.w};
            float br[4] = {b0.x,b0.y,b0.z,b0.w};
            #pragma unroll
            for (int i = 0; i < 8; i++)
                #pragma unroll
                for (int j = 0; j < 4; j++)
                    acc[i][j] = fmaf(ar[i], br[j], acc[i][j]);
        }
        if (c + 1 < nch) {
            float* Asw = u.s.As[buf^1]; float* Bsw = u.s.Bs[buf^1];
            Asw[(akq+0)*AS_STRIDE+am]=na0.x; Asw[(akq+1)*AS_STRIDE+am]=na0.y;
            Asw[(akq+2)*AS_STRIDE+am]=na0.z; Asw[(akq+3)*AS_STRIDE+am]=na0.w;
            Asw[(akq+4)*AS_STRIDE+am]=na1.x; Asw[(akq+5)*AS_STRIDE+am]=na1.y;
            Asw[(akq+6)*AS_STRIDE+am]=na1.z; Asw[(akq+7)*AS_STRIDE+am]=na1.w;
            Bsw[(bkq+0)*BS_STRIDE+bn]=nb0.x; Bsw[(bkq+1)*BS_STRIDE+bn]=nb0.y;
            Bsw[(bkq+2)*BS_STRIDE+bn]=nb0.z; Bsw[(bkq+3)*BS_STRIDE+bn]=nb0.w;
            buf ^= 1;
        }
    }

    bool transp = is_c || (n0 < DI);
    if (transp) {
        __syncthreads();
        #pragma unroll
        for (int i = 0; i < 8; i++)
            #pragma unroll
            for (int j = 0; j < 4; j++)
                u.Ts[(tx*4+j)*129 + ty*8+i] = acc[i][j];
        __syncthreads();
        int b = m0 >> 12, l0 = m0 & 4095;
        float* dst = is_c ? g_c_pre : g_xa_pre;
        for (int e = tid; e < 64*128; e += 256) {
            int row = e >> 7, cc = e & 127;
            dst[((size_t)(b*DI + nb + row))*LL + l0 + cc] = u.Ts[row*129 + cc];
        }
    } else {
        #pragma unroll
        for (int i = 0; i < 8; i++) {
            int m = m0 + ty*8 + i;
            #pragma unroll
            for (int j = 0; j < 4; j++) {
                int nz = n0 - DI + tx*4 + j;
                g_z[(size_t)m*DI + nz] = silu_f(acc[i][j]);
            }
        }
    }
}

// =======================================================================
// gemm_out: out = LN(y)*z @ W_out^T, LN applied on the fly from g_stats.
// =======================================================================
__global__ void __launch_bounds__(256) gemm_out_k(const float* __restrict__ Bw,
        const float* __restrict__ ln_w, const float* __restrict__ ln_b,
        float* __restrict__ out)
{
    __shared__ __align__(16) float As[2][16*AS_STRIDE];
    __shared__ __align__(16) float Bs[2][16*BS_STRIDE];

    const int K = DI, N = DM;
    int tid = threadIdx.x;
    int tx = tid & 15, ty = tid >> 4;
    int n0 = blockIdx.x * 64;
    int m0 = blockIdx.y * 128;

    int am  = tid >> 1;
    int akq = (tid & 1) * 8;
    int bn  = tid >> 2;
    int bkq = (tid & 3) * 4;
    const float* yP = g_y + (size_t)(m0 + am) * K + akq;
    const float* zP = g_z + (size_t)(m0 + am) * K + akq;
    const float* bP = Bw  + (size_t)(n0 + bn) * K + bkq;
    float2 st = g_stats[m0 + am];   // mu, rstd

    float acc[8][4];
    #pragma unroll
    for (int i = 0; i < 8; i++)
        #pragma unroll
        for (int j = 0; j < 4; j++) acc[i][j] = 0.f;

    // fused A element loader
    #define LOADA(c, r0, r1)                                                   \
    {                                                                          \
        int k = (c)*16;                                                        \
        float4 y0 = *(const float4*)(yP + k);                                  \
        float4 y1 = *(const float4*)(yP + k + 4);                              \
        float4 z0 = *(const float4*)(zP + k);                                  \
        float4 z1 = *(const float4*)(zP + k + 4);                              \
        float4 w0 = *(const float4*)(ln_w + k + akq);                          \
        float4 w1 = *(const float4*)(ln_w + k + akq + 4);                      \
        float4 lb0 = *(const float4*)(ln_b + k + akq);                         \
        float4 lb1 = *(const float4*)(ln_b + k + akq + 4);                     \
        r0.x = ((y0.x-st.x)*st.y*w0.x + lb0.x)*z0.x;                           \
        r0.y = ((y0.y-st.x)*st.y*w0.y + lb0.y)*z0.y;                           \
        r0.z = ((y0.z-st.x)*st.y*w0.z + lb0.z)*z0.z;                           \
        r0.w = ((y0.w-st.x)*st.y*w0.w + lb0.w)*z0.w;                           \
        r1.x = ((y1.x-st.x)*st.y*w1.x + lb1.x)*z1.x;                           \
        r1.y = ((y1.y-st.x)*st.y*w1.y + lb1.y)*z1.y;                           \
        r1.z = ((y1.z-st.x)*st.y*w1.z + lb1.z)*z1.z;                           \
        r1.w = ((y1.w-st.x)*st.y*w1.w + lb1.w)*z1.w;                           \
    }

    {
        float4 a0, a1;
        LOADA(0, a0, a1);
        float4 b0 = *(const float4*)(bP);
        As[0][(akq+0)*AS_STRIDE+am]=a0.x; As[0][(akq+1)*AS_STRIDE+am]=a0.y;
        As[0][(akq+2)*AS_STRIDE+am]=a0.z; As[0][(akq+3)*AS_STRIDE+am]=a0.w;
        As[0][(akq+4)*AS_STRIDE+am]=a1.x; As[0][(akq+5)*AS_STRIDE+am]=a1.y;
        As[0][(akq+6)*AS_STRIDE+am]=a1.z; As[0][(akq+7)*AS_STRIDE+am]=a1.w;
        Bs[0][(bkq+0)*BS_STRIDE+bn]=b0.x; Bs[0][(bkq+1)*BS_STRIDE+bn]=b0.y;
        Bs[0][(bkq+2)*BS_STRIDE+bn]=b0.z; Bs[0][(bkq+3)*BS_STRIDE+bn]=b0.w;
    }

    int buf = 0;
    const int nch = K / 16;   // 24
    for (int c = 0; c < nch; c++) {
        float4 na0, na1, nb0;
        if (c + 1 < nch) {
            LOADA(c+1, na0, na1);
            nb0 = *(const float4*)(bP + (c+1)*16);
        }
        __syncthreads();
        const float* Asr = As[buf];
        const float* Bsr = Bs[buf];
        #pragma unroll
        for (int kk = 0; kk < 16; kk++) {
            float4 a0 = *(const float4*)&Asr[kk*AS_STRIDE + ty*8];
            float4 a1 = *(const float4*)&Asr[kk*AS_STRIDE + ty*8 + 4];
            float4 b0 = *(const float4*)&Bsr[kk*BS_STRIDE + tx*4];
            float ar[8] = {a0.x,a0.y,a0.z,a0.w,a1.x,a1.y,a1.z,a1.w};
            float br[4] = {b0.x,b0.y,b0.z,b0.w};
            #pragma unroll
            for (int i = 0; i < 8; i++)
                #pragma unroll
                for (int j = 0; j < 4; j++)
                    acc[i][j] = fmaf(ar[i], br[j], acc[i][j]);
        }
        if (c + 1 < nch) {
            float* Asw = As[buf^1]; float* Bsw = Bs[buf^1];
            Asw[(akq+0)*AS_STRIDE+am]=na0.x; Asw[(akq+1)*AS_STRIDE+am]=na0.y;
            Asw[(akq+2)*AS_STRIDE+am]=na0.z; Asw[(akq+3)*AS_STRIDE+am]=na0.w;
            Asw[(akq+4)*AS_STRIDE+am]=na1.x; Asw[(akq+5)*AS_STRIDE+am]=na1.y;
            Asw[(akq+6)*AS_STRIDE+am]=na1.z; Asw[(akq+7)*AS_STRIDE+am]=na1.w;
            Bsw[(bkq+0)*BS_STRIDE+bn]=nb0.x; Bsw[(bkq+1)*BS_STRIDE+bn]=nb0.y;
            Bsw[(bkq+2)*BS_STRIDE+bn]=nb0.z; Bsw[(bkq+3)*BS_STRIDE+bn]=nb0.w;
            buf ^= 1;
        }
    }
    #undef LOADA

    #pragma unroll
    for (int i = 0; i < 8; i++) {
        int m = m0 + ty*8 + i;
        #pragma unroll
        for (int j = 0; j < 4; j++) {
            int n = n0 + tx*4 + j;
            out[(size_t)m*N + n] = acc[i][j];
        }
    }
}

// =======================================================================
// per-row LN stats: mu, rstd
// =======================================================================
__global__ void __launch_bounds__(256) ln_stats_k()
{
    int row = blockIdx.x * 8 + (threadIdx.x >> 5);
    int lane = threadIdx.x & 31;
    const float* yr = g_y + (size_t)row * DI;
    float s = 0.f, q = 0.f;
    #pragma unroll
    for (int i = 0; i < 12; i++) {
        float v = yr[lane + 32*i];
        s += v; q += v*v;
    }
    #pragma unroll
    for (int o = 16; o > 0; o >>= 1) {
        s += __shfl_xor_sync(0xFFFFFFFFu, s, o);
        q += __shfl_xor_sync(0xFFFFFFFFu, q, o);
    }
    if (lane == 0) {
        float mu = s * (1.f / DI);
        float var = q * (1.f / DI) - mu*mu;
        g_stats[row] = make_float2(mu, rsqrtf(var + 1e-5f));
    }
}

// =======================================================================
// depthwise conv 3x3 SAME + bias + silu for BOTH tensors
// =======================================================================
__global__ void __launch_bounds__(256) dwconv_k(const float* __restrict__ conv_w,
        const float* __restrict__ conv_b, const float* __restrict__ con_w,
        const float* __restrict__ con_b)
{
    __shared__ __align__(16) float imx[LL];
    __shared__ __align__(16) float imc[LL];
    int bd = blockIdx.x;
    int d  = bd % DI;
    const float* inx = g_xa_pre + (size_t)bd * LL;
    const float* inc = g_c_pre  + (size_t)bd * LL;
    float* outx = g_xa_conv + (size_t)bd * LL;
    float* outs = g_s       + (size_t)bd * LL;
    const float* wxp = conv_w + d * 9;
    const float* wcp = con_w  + d * 9;
    float bx = conv_b[d], bc = con_b[d];

    #pragma unroll
    for (int i = 0; i < 4; i++) {
        *(float4*)&imx[(threadIdx.x + 256*i)*4] = *(const float4*)&inx[(threadIdx.x + 256*i)*4];
        *(float4*)&imc[(threadIdx.x + 256*i)*4] = *(const float4*)&inc[(threadIdx.x + 256*i)*4];
    }
    float wx[9], wc[9];
    #pragma unroll
    for (int i = 0; i < 9; i++) { wx[i] = wxp[i]; wc[i] = wcp[i]; }
    __syncthreads();

    #pragma unroll
    for (int i = 0; i < 16; i++) {
        int l = threadIdx.x + 256*i;
        int y = l >> 6, x = l & 63;
        bool yl = y > 0, yh = y < 63, xl = x > 0, xh = x < 63;
        float ax = bx, ac = bc;
        if (yl) {
            if (xl) { ax = fmaf(imx[l-65], wx[0], ax); ac = fmaf(imc[l-65], wc[0], ac); }
            ax = fmaf(imx[l-64], wx[1], ax); ac = fmaf(imc[l-64], wc[1], ac);
            if (xh) { ax = fmaf(imx[l-63], wx[2], ax); ac = fmaf(imc[l-63], wc[2], ac); }
        }
        if (xl) { ax = fmaf(imx[l-1], wx[3], ax); ac = fmaf(imc[l-1], wc[3], ac); }
        ax = fmaf(imx[l], wx[4], ax); ac = fmaf(imc[l], wc[4], ac);
        if (xh) { ax = fmaf(imx[l+1], wx[5], ax); ac = fmaf(imc[l+1], wc[5], ac); }
        if (yh) {
            if (xl) { ax = fmaf(imx[l+63], wx[6], ax); ac = fmaf(imc[l+63], wc[6], ac); }
            ax = fmaf(imx[l+64], wx[7], ax); ac = fmaf(imc[l+64], wc[7], ac);
            if (xh) { ax = fmaf(imx[l+65], wx[8], ax); ac = fmaf(imc[l+65], wc[8], ac); }
        }
        float sa = silu_f(ax);
        outx[l] = sa;
        outs[l] = sa + silu_f(ac);
    }
}

// =======================================================================
// proj: 64 px/block; 3-stage cp.async stage 1; 3-stage cp.async stage 2.
// =======================================================================
__global__ void __launch_bounds__(256) proj_k(const float* __restrict__ x_proj_w,
        const float* __restrict__ dt_proj_w, const float* __restrict__ dt_proj_b,
        const int* __restrict__ rev_scan)
{
    __shared__ float xd[64*49];
    __shared__ __align__(16) union {
        struct { float sS[3][16*68]; float sB[3][16*48]; } a;
        float xaT[3][32*68];
    } u;

    int tid = threadIdx.x;
    int b   = blockIdx.x >> 6;
    int l0  = (blockIdx.x & 63) * 64;

    // zero sB pads (cc>=44 never written by cp.async)
    for (int e = tid; e < 3*16*48; e += 256) (&u.a.sB[0][0])[e] = 0.f;

    unsigned sS_b = (unsigned)__cvta_generic_to_shared(&u.a.sS[0][0]);
    unsigned sB_b = (unsigned)__cvta_generic_to_shared(&u.a.sB[0][0]);
    unsigned xa_b = (unsigned)__cvta_generic_to_shared(&u.xaT[0][0]);

    #define S1_PREFETCH(kc, bf)                                                \
    {                                                                          \
        int k = tid >> 4, px4 = tid & 15;                                      \
        cpa16(sS_b + (unsigned)(((bf)*16*68 + k*68 + px4*4)*4),                \
              g_s + ((size_t)(b*DI + (kc)*16 + k))*LL + l0 + px4*4);           \
        _Pragma("unroll")                                                      \
        for (int i = 0; i < 3; i++) {                                          \
            int e = tid + 256*i;                                               \
            int cc = e >> 4, kk = e & 15;                                      \
            if (cc < DR + 2*DS)                                                \
                cpa4(sB_b + (unsigned)(((bf)*16*48 + kk*48 + cc)*4),           \
                     x_proj_w + (size_t)cc*DI + (kc)*16 + kk);                 \
        }                                                                      \
    }
    #define S2_PREFETCH(cc, bf)                                                \
    {                                                                          \
        _Pragma("unroll")                                                      \
        for (int i = 0; i < 2; i++) {                                          \
            int e = tid + 256*i;                                               \
            int dd = e >> 4, px4 = e & 15;                                     \
            cpa16(xa_b + (unsigned)(((bf)*32*68 + dd*68 + px4*4)*4),           \
                  g_xa_conv + ((size_t)(b*DI + (cc)*32 + dd))*LL + l0 + px4*4);\
        }                                                                      \
    }

    __syncthreads();   // sB pad zeros visible before any compute reads pads

    S1_PREFETCH(0, 0); cp_commit();
    S1_PREFETCH(1, 1); cp_commit();

    int tm = tid & 15, tn = tid >> 4;
    float acc[4][3];
    #pragma unroll
    for (int i = 0; i < 4; i++)
        #pragma unroll
        for (int j = 0; j < 3; j++) acc[i][j] = 0.f;

    const int NC1 = DI/16;   // 24
    for (int kc = 0; kc < NC1; kc++) {
        if (kc < NC1-1) cp_wait1(); else cp_wait0();
        __syncthreads();
        if (kc + 2 < NC1) { S1_PREFETCH(kc+2, (kc+2)%3); cp_commit(); }
        const float* sS = u.a.sS[kc%3];
        const float* sB = u.a.sB[kc%3];
        #pragma unroll
        for (int k = 0; k < 16; k++) {
            float4 av = *(const float4*)&sS[k*68 + tm*4];
            float b0 = sB[k*48 + tn*3 + 0];
            float b1 = sB[k*48 + tn*3 + 1];
            float b2 = sB[k*48 + tn*3 + 2];
            float ar[4] = {av.x, av.y, av.z, av.w};
            #pragma unroll
            for (int i = 0; i < 4; i++) {
                acc[i][0] = fmaf(ar[i], b0, acc[i][0]);
                acc[i][1] = fmaf(ar[i], b1, acc[i][1]);
                acc[i][2] = fmaf(ar[i], b2, acc[i][2]);
            }
        }
    }
    #pragma unroll
    for (int i = 0; i < 4; i++)
        #pragma unroll
        for (int j = 0; j < 3; j++)
            xd[(tm*4+i)*49 + tn*3+j] = acc[i][j];
    __syncthreads();   // all sS reads done; xd visible

    // stage-2 prefetch starts now, overlapping B/C scatter
    S2_PREFETCH(0, 0); cp_commit();
    S2_PREFETCH(1, 1); cp_commit();

    int w = tid >> 5, lane = tid & 31;

    #pragma unroll
    for (int p = 0; p < 4; p++) {
        int px = w*8 + p*2 + (lane >> 4);
        int n  = lane & 15;
        int j  = __ldg(&rev_scan[l0 + px]);
        g_bc[((size_t)b*LL + j)*DS + n] =
            make_float2(xd[px*49 + DR + n], xd[px*49 + DR + DS + n]);
    }

    const int NC2 = DI/32;   // 12
    for (int c32 = 0; c32 < NC2; c32++) {
        if (c32 < NC2-1) cp_wait1(); else cp_wait0();
        __syncthreads();
        if (c32 + 2 < NC2) { S2_PREFETCH(c32+2, (c32+2)%3); cp_commit(); }
        int d = c32*32 + lane;
        float wr[DR];
        #pragma unroll
        for (int r = 0; r < DR; r++) wr[r] = __ldg(&dt_proj_w[(size_t)d*DR + r]);
        float bias = __ldg(&dt_proj_b[d]);
        const float* xaT = u.xaT[c32%3];
        #pragma unroll
        for (int p = 0; p < 8; p++) {
            int px = p*8 + w;
            float a = bias;
            #pragma unroll
            for (int r = 0; r < DR; r++) a = fmaf(wr[r], xd[px*49 + r], a);
            float delta = (a > 20.f) ? a : log1pf(__expf(a));
            float uval  = xaT[lane*68 + px];
            int j = __ldg(&rev_scan[l0 + px]);
            g_du[((size_t)b*LL + j)*DI + d] = make_float2(delta, uval);
        }
    }
    #undef S1_PREFETCH
    #undef S2_PREFETCH
}

// =======================================================================
// selective scan: block = 8 channels of one batch, 128 thr
// =======================================================================
#define TSTEP 32
#define NTILE (LL/TSTEP)   // 128

__global__ void __launch_bounds__(128) scan_k(const float* __restrict__ A_logs,
        const float* __restrict__ Ds, const int* __restrict__ scan_path)
{
    __shared__ __align__(16) float2 du2[2][TSTEP][8];
    __shared__ __align__(16) float2 bc2[2][TSTEP][DS];
    __shared__ float  ps[TSTEP*8*17];
    __shared__ float  s_D[8];

    int tid = threadIdx.x;
    int b   = blockIdx.x / 48;
    int d0  = (blockIdx.x % 48) * 8;
    int wid = tid >> 5, lane = tid & 31;
    int g = lane >> 4, n = lane & 15;
    int ch = wid*2 + g;
    int d = d0 + ch;

    float a_coef = -__expf(A_logs[d*DS + n]);
    if (tid < 8) s_D[tid] = Ds[d0 + tid];

    unsigned du_sm = (unsigned)__cvta_generic_to_shared(&du2[0][0][0]);
    unsigned bc_sm = (unsigned)__cvta_generic_to_shared(&bc2[0][0][0]);
    const float2* du_g = g_du + (size_t)b*LL*DI + d0;
    const float2* bc_g = g_bc + (size_t)b*LL*DS;

    {
        #pragma unroll
        for (int i = 0; i < 2; i++) {
            int e = tid + 128*i;
            int jj = e >> 3, c = e & 7;
            cpa8(du_sm + (unsigned)((jj*8 + c)*8), du_g + (size_t)jj*DI + c);
        }
        #pragma unroll
        for (int i = 0; i < 2; i++) {
            int e = tid + 128*i;
            int jj = e >> 3, q = e & 7;
            cpa16(bc_sm + (unsigned)((jj*DS + q*2)*8), bc_g + (size_t)jj*DS + q*2);
        }
        cp_commit();
    }

    float h = 0.f;
    int buf = 0;
    for (int T = 0; T < NTILE; T++) {
        if (T + 1 < NTILE) {
            int o = (buf^1) * TSTEP;
            #pragma unroll
            for (int i = 0; i < 2; i++) {
                int e = tid + 128*i;
                int jj = e >> 3, c = e & 7;
                cpa8(du_sm + (unsigned)(((o+jj)*8 + c)*8),
                     du_g + (size_t)((T+1)*TSTEP + jj)*DI + c);
            }
            #pragma unroll
            for (int i = 0; i < 2; i++) {
                int e = tid + 128*i;
                int jj = e >> 3, q = e & 7;
                cpa16(bc_sm + (unsigned)(((o+jj)*DS + q*2)*8),
                      bc_g + (size_t)((T+1)*TSTEP + jj)*DS + q*2);
            }
            cp_commit();
            cp_wait1();
        } else {
            cp_wait0();
        }
        __syncthreads();

        #pragma unroll 8
        for (int jj = 0; jj < TSTEP; jj++) {
            float2 du = du2[buf][jj][ch];
            float2 bc = bc2[buf][jj][n];
            float dA = __expf(du.x * a_coef);
            h = fmaf(dA, h, du.x * du.y * bc.x);
            ps[(jj*8 + ch)*17 + n] = h * bc.y;
        }
        __syncthreads();

        #pragma unroll
        for (int i = 0; i < 2; i++) {
            int e = tid + 128*i;
            int jj = e >> 3, c = e & 7;
            const float* p = &ps[(jj*8 + c)*17];
            float sum = p[0];
            #pragma unroll
            for (int k = 1; k < DS; k++) sum += p[k];
            float uval = du2[buf][jj][c].y;
            int pos = __ldg(&scan_path[T*TSTEP + jj]);
            g_y[((size_t)b*LL + pos)*DI + d0 + c] = fmaf(uval, s_D[c], sum);
        }
        buf ^= 1;
    }
}

// ---------------- launch ----------------
extern "C" void kernel_launch(void* const* d_in, const int* in_sizes, int n_in,
                              void* d_out, int out_size)
{
    const float* x          = (const float*)d_in[0];
    const float* cond       = (const float*)d_in[1];
    const float* W_in       = (const float*)d_in[2];
    const float* W_con      = (const float*)d_in[3];
    const float* conv_w     = (const float*)d_in[4];
    const float* conv_b     = (const float*)d_in[5];
    const float* con_conv_w = (const float*)d_in[6];
    const float* con_conv_b = (const float*)d_in[7];
    const float* x_proj_w   = (const float*)d_in[8];
    const float* dt_proj_w  = (const float*)d_in[9];
    const float* dt_proj_b  = (const float*)d_in[10];
    const float* A_logs     = (const float*)d_in[11];
    const float* Ds         = (const float*)d_in[12];
    const float* ln_w       = (const float*)d_in[13];
    const float* ln_b       = (const float*)d_in[14];
    const float* W_out      = (const float*)d_in[15];
    const int*   scan_path  = (const int*)d_in[16];
    const int*   rev_scan   = (const int*)d_in[17];
    float* out = (float*)d_out;

    gemm_in_k<<<dim3(3*DI/64, NROWS/128), 256>>>(x, cond, W_in, W_con);
    dwconv_k<<<BB*DI, 256>>>(conv_w, conv_b, con_conv_w, con_conv_b);
    proj_k<<<NROWS/64, 256>>>(x_proj_w, dt_proj_w, dt_proj_b, rev_scan);
    scan_k<<<(BB*DI)/8, 128>>>(A_logs, Ds, scan_path);
    ln_stats_k<<<NROWS/8, 256>>>();
    gemm_out_k<<<dim3(DM/64, NROWS/128), 256>>>(W_out, ln_w, ln_b, out);
}

// round 8
// speedup vs baseline: 1.7386x; 1.5462x over previous
#include <cuda_runtime.h>

#define BB 2
#define DM 192
#define DI 384
#define DS 16
#define DR 12
#define HH 64
#define WW 64
#define LL 4096
#define NROWS (BB*LL)   // 8192

#define TSTEP 32
#define CH 16
#define CL (LL/CH)          // 256 steps per chunk
#define PTILES (CL/TSTEP)   // 8 tiles per chunk

// ---------------- scratch ----------------
__device__ float  g_xa_pre[BB*DI*LL];
__device__ float  g_c_pre [BB*DI*LL];
__device__ float  g_xa_conv[BB*DI*LL];
__device__ float  g_s     [BB*DI*LL];
__device__ float  g_z     [NROWS*DI];
__device__ float2 g_du    [BB*LL*DI];
__device__ float2 g_bc    [BB*LL*DS];
__device__ float  g_y     [NROWS*DI];
__device__ float2 g_stats [NROWS];
__device__ float  g_E     [BB*CH*DI*DS];   // chunk end states (from 0)
__device__ float  g_Ssum  [BB*CH*DI];      // sum of delta per chunk
__device__ float  g_hin   [BB*CH*DI*DS];   // chunk initial states

__device__ __forceinline__ float silu_f(float v){ return v / (1.f + __expf(-v)); }

__device__ __forceinline__ void cpa4(unsigned dst, const void* src){
    asm volatile("cp.async.ca.shared.global [%0], [%1], 4;\n" :: "r"(dst), "l"(src));
}
__device__ __forceinline__ void cpa8(unsigned dst, const void* src){
    asm volatile("cp.async.ca.shared.global [%0], [%1], 8;\n" :: "r"(dst), "l"(src));
}
__device__ __forceinline__ void cpa16(unsigned dst, const void* src){
    asm volatile("cp.async.ca.shared.global [%0], [%1], 16;\n" :: "r"(dst), "l"(src));
}
__device__ __forceinline__ void cp_commit(){ asm volatile("cp.async.commit_group;\n"); }
__device__ __forceinline__ void cp_wait1(){ asm volatile("cp.async.wait_group 1;\n"); }
__device__ __forceinline__ void cp_wait0(){ asm volatile("cp.async.wait_group 0;\n"); }

#define AS_STRIDE 132
#define BS_STRIDE 68

// =======================================================================
// gemm_in: BOTH input GEMMs in one launch. 128x64 tile, 8x4 micro.
// =======================================================================
__global__ void __launch_bounds__(256) gemm_in_k(const float* __restrict__ x,
        const float* __restrict__ cond, const float* __restrict__ W_in,
        const float* __restrict__ W_con)
{
    __shared__ __align__(16) union {
        struct { float As[2][16*AS_STRIDE]; float Bs[2][16*BS_STRIDE]; } s;
        float Ts[64*129];
    } u;

    const int K = DM;
    int tid = threadIdx.x;
    int tx = tid & 15, ty = tid >> 4;
    int n0 = blockIdx.x * 64;
    int m0 = blockIdx.y * 128;
    bool is_c = (n0 >= 2*DI);
    const float* A  = is_c ? cond  : x;
    const float* Bw = is_c ? W_con : W_in;
    int nb = is_c ? n0 - 2*DI : n0;

    int am  = tid >> 1;
    int akq = (tid & 1) * 8;
    int bn  = tid >> 2;
    int bkq = (tid & 3) * 4;
    const float* aP = A  + (size_t)(m0 + am) * K + akq;
    const float* bP = Bw + (size_t)(nb + bn) * K + bkq;

    float acc[8][4];
    #pragma unroll
    for (int i = 0; i < 8; i++)
        #pragma unroll
        for (int j = 0; j < 4; j++) acc[i][j] = 0.f;

    {
        float4 a0 = *(const float4*)(aP);
        float4 a1 = *(const float4*)(aP + 4);
        float4 b0 = *(const float4*)(bP);
        float* As = u.s.As[0]; float* Bs = u.s.Bs[0];
        As[(akq+0)*AS_STRIDE+am]=a0.x; As[(akq+1)*AS_STRIDE+am]=a0.y;
        As[(akq+2)*AS_STRIDE+am]=a0.z; As[(akq+3)*AS_STRIDE+am]=a0.w;
        As[(akq+4)*AS_STRIDE+am]=a1.x; As[(akq+5)*AS_STRIDE+am]=a1.y;
        As[(akq+6)*AS_STRIDE+am]=a1.z; As[(akq+7)*AS_STRIDE+am]=a1.w;
        Bs[(bkq+0)*BS_STRIDE+bn]=b0.x; Bs[(bkq+1)*BS_STRIDE+bn]=b0.y;
        Bs[(bkq+2)*BS_STRIDE+bn]=b0.z; Bs[(bkq+3)*BS_STRIDE+bn]=b0.w;
    }

    int buf = 0;
    const int nch = K / 16;
    for (int c = 0; c < nch; c++) {
        float4 na0, na1, nb0;
        if (c + 1 < nch) {
            na0 = *(const float4*)(aP + (c+1)*16);
            na1 = *(const float4*)(aP + (c+1)*16 + 4);
            nb0 = *(const float4*)(bP + (c+1)*16);
        }
        __syncthreads();
        const float* As = u.s.As[buf];
        const float* Bs = u.s.Bs[buf];
        #pragma unroll
        for (int kk = 0; kk < 16; kk++) {
            float4 a0 = *(const float4*)&As[kk*AS_STRIDE + ty*8];
            float4 a1 = *(const float4*)&As[kk*AS_STRIDE + ty*8 + 4];
            float4 b0 = *(const float4*)&Bs[kk*BS_STRIDE + tx*4];
            float ar[8] = {a0.x,a0.y,a0.z,a0.w,a1.x,a1.y,a1.z,a1.w};
            float br[4] = {b0.x,b0.y,b0.z,b0.w};
            #pragma unroll
            for (int i = 0; i < 8; i++)
                #pragma unroll
                for (int j = 0; j < 4; j++)
                    acc[i][j] = fmaf(ar[i], br[j], acc[i][j]);
        }
        if (c + 1 < nch) {
            float* Asw = u.s.As[buf^1]; float* Bsw = u.s.Bs[buf^1];
            Asw[(akq+0)*AS_STRIDE+am]=na0.x; Asw[(akq+1)*AS_STRIDE+am]=na0.y;
            Asw[(akq+2)*AS_STRIDE+am]=na0.z; Asw[(akq+3)*AS_STRIDE+am]=na0.w;
            Asw[(akq+4)*AS_STRIDE+am]=na1.x; Asw[(akq+5)*AS_STRIDE+am]=na1.y;
            Asw[(akq+6)*AS_STRIDE+am]=na1.z; Asw[(akq+7)*AS_STRIDE+am]=na1.w;
            Bsw[(bkq+0)*BS_STRIDE+bn]=nb0.x; Bsw[(bkq+1)*BS_STRIDE+bn]=nb0.y;
            Bsw[(bkq+2)*BS_STRIDE+bn]=nb0.z; Bsw[(bkq+3)*BS_STRIDE+bn]=nb0.w;
            buf ^= 1;
        }
    }

    bool transp = is_c || (n0 < DI);
    if (transp) {
        __syncthreads();
        #pragma unroll
        for (int i = 0; i < 8; i++)
            #pragma unroll
            for (int j = 0; j < 4; j++)
                u.Ts[(tx*4+j)*129 + ty*8+i] = acc[i][j];
        __syncthreads();
        int b = m0 >> 12, l0 = m0 & 4095;
        float* dst = is_c ? g_c_pre : g_xa_pre;
        for (int e = tid; e < 64*128; e += 256) {
            int row = e >> 7, cc = e & 127;
            dst[((size_t)(b*DI + nb + row))*LL + l0 + cc] = u.Ts[row*129 + cc];
        }
    } else {
        #pragma unroll
        for (int i = 0; i < 8; i++) {
            int m = m0 + ty*8 + i;
            #pragma unroll
            for (int j = 0; j < 4; j++) {
                int nz = n0 - DI + tx*4 + j;
                g_z[(size_t)m*DI + nz] = silu_f(acc[i][j]);
            }
        }
    }
}

// =======================================================================
// gemm_out: out = LN(y)*z @ W_out^T, LN applied on the fly.
// =======================================================================
__global__ void __launch_bounds__(256) gemm_out_k(const float* __restrict__ Bw,
        const float* __restrict__ ln_w, const float* __restrict__ ln_b,
        float* __restrict__ out)
{
    __shared__ __align__(16) float As[2][16*AS_STRIDE];
    __shared__ __align__(16) float Bs[2][16*BS_STRIDE];

    const int K = DI, N = DM;
    int tid = threadIdx.x;
    int tx = tid & 15, ty = tid >> 4;
    int n0 = blockIdx.x * 64;
    int m0 = blockIdx.y * 128;

    int am  = tid >> 1;
    int akq = (tid & 1) * 8;
    int bn  = tid >> 2;
    int bkq = (tid & 3) * 4;
    const float* yP = g_y + (size_t)(m0 + am) * K + akq;
    const float* zP = g_z + (size_t)(m0 + am) * K + akq;
    const float* bP = Bw  + (size_t)(n0 + bn) * K + bkq;
    float2 st = g_stats[m0 + am];

    float acc[8][4];
    #pragma unroll
    for (int i = 0; i < 8; i++)
        #pragma unroll
        for (int j = 0; j < 4; j++) acc[i][j] = 0.f;

    #define LOADA(c, r0, r1)                                                   \
    {                                                                          \
        int k = (c)*16;                                                        \
        float4 y0 = *(const float4*)(yP + k);                                  \
        float4 y1 = *(const float4*)(yP + k + 4);                              \
        float4 z0 = *(const float4*)(zP + k);                                  \
        float4 z1 = *(const float4*)(zP + k + 4);                              \
        float4 w0 = *(const float4*)(ln_w + k + akq);                          \
        float4 w1 = *(const float4*)(ln_w + k + akq + 4);                      \
        float4 lb0 = *(const float4*)(ln_b + k + akq);                         \
        float4 lb1 = *(const float4*)(ln_b + k + akq + 4);                     \
        r0.x = ((y0.x-st.x)*st.y*w0.x + lb0.x)*z0.x;                           \
        r0.y = ((y0.y-st.x)*st.y*w0.y + lb0.y)*z0.y;                           \
        r0.z = ((y0.z-st.x)*st.y*w0.z + lb0.z)*z0.z;                           \
        r0.w = ((y0.w-st.x)*st.y*w0.w + lb0.w)*z0.w;                           \
        r1.x = ((y1.x-st.x)*st.y*w1.x + lb1.x)*z1.x;                           \
        r1.y = ((y1.y-st.x)*st.y*w1.y + lb1.y)*z1.y;                           \
        r1.z = ((y1.z-st.x)*st.y*w1.z + lb1.z)*z1.z;                           \
        r1.w = ((y1.w-st.x)*st.y*w1.w + lb1.w)*z1.w;                           \
    }

    {
        float4 a0, a1;
        LOADA(0, a0, a1);
        float4 b0 = *(const float4*)(bP);
        As[0][(akq+0)*AS_STRIDE+am]=a0.x; As[0][(akq+1)*AS_STRIDE+am]=a0.y;
        As[0][(akq+2)*AS_STRIDE+am]=a0.z; As[0][(akq+3)*AS_STRIDE+am]=a0.w;
        As[0][(akq+4)*AS_STRIDE+am]=a1.x; As[0][(akq+5)*AS_STRIDE+am]=a1.y;
        As[0][(akq+6)*AS_STRIDE+am]=a1.z; As[0][(akq+7)*AS_STRIDE+am]=a1.w;
        Bs[0][(bkq+0)*BS_STRIDE+bn]=b0.x; Bs[0][(bkq+1)*BS_STRIDE+bn]=b0.y;
        Bs[0][(bkq+2)*BS_STRIDE+bn]=b0.z; Bs[0][(bkq+3)*BS_STRIDE+bn]=b0.w;
    }

    int buf = 0;
    const int nch = K / 16;
    for (int c = 0; c < nch; c++) {
        float4 na0, na1, nb0;
        if (c + 1 < nch) {
            LOADA(c+1, na0, na1);
            nb0 = *(const float4*)(bP + (c+1)*16);
        }
        __syncthreads();
        const float* Asr = As[buf];
        const float* Bsr = Bs[buf];
        #pragma unroll
        for (int kk = 0; kk < 16; kk++) {
            float4 a0 = *(const float4*)&Asr[kk*AS_STRIDE + ty*8];
            float4 a1 = *(const float4*)&Asr[kk*AS_STRIDE + ty*8 + 4];
            float4 b0 = *(const float4*)&Bsr[kk*BS_STRIDE + tx*4];
            float ar[8] = {a0.x,a0.y,a0.z,a0.w,a1.x,a1.y,a1.z,a1.w};
            float br[4] = {b0.x,b0.y,b0.z,b0.w};
            #pragma unroll
            for (int i = 0; i < 8; i++)
                #pragma unroll
                for (int j = 0; j < 4; j++)
                    acc[i][j] = fmaf(ar[i], br[j], acc[i][j]);
        }
        if (c + 1 < nch) {
            float* Asw = As[buf^1]; float* Bsw = Bs[buf^1];
            Asw[(akq+0)*AS_STRIDE+am]=na0.x; Asw[(akq+1)*AS_STRIDE+am]=na0.y;
            Asw[(akq+2)*AS_STRIDE+am]=na0.z; Asw[(akq+3)*AS_STRIDE+am]=na0.w;
            Asw[(akq+4)*AS_STRIDE+am]=na1.x; Asw[(akq+5)*AS_STRIDE+am]=na1.y;
            Asw[(akq+6)*AS_STRIDE+am]=na1.z; Asw[(akq+7)*AS_STRIDE+am]=na1.w;
            Bsw[(bkq+0)*BS_STRIDE+bn]=nb0.x; Bsw[(bkq+1)*BS_STRIDE+bn]=nb0.y;
            Bsw[(bkq+2)*BS_STRIDE+bn]=nb0.z; Bsw[(bkq+3)*BS_STRIDE+bn]=nb0.w;
            buf ^= 1;
        }
    }
    #undef LOADA

    #pragma unroll
    for (int i = 0; i < 8; i++) {
        int m = m0 + ty*8 + i;
        #pragma unroll
        for (int j = 0; j < 4; j++) {
            int n = n0 + tx*4 + j;
            out[(size_t)m*N + n] = acc[i][j];
        }
    }
}

// =======================================================================
// per-row LN stats
// =======================================================================
__global__ void __launch_bounds__(256) ln_stats_k()
{
    int row = blockIdx.x * 8 + (threadIdx.x >> 5);
    int lane = threadIdx.x & 31;
    const float* yr = g_y + (size_t)row * DI;
    float s = 0.f, q = 0.f;
    #pragma unroll
    for (int i = 0; i < 12; i++) {
        float v = yr[lane + 32*i];
        s += v; q += v*v;
    }
    #pragma unroll
    for (int o = 16; o > 0; o >>= 1) {
        s += __shfl_xor_sync(0xFFFFFFFFu, s, o);
        q += __shfl_xor_sync(0xFFFFFFFFu, q, o);
    }
    if (lane == 0) {
        float mu = s * (1.f / DI);
        float var = q * (1.f / DI) - mu*mu;
        g_stats[row] = make_float2(mu, rsqrtf(var + 1e-5f));
    }
}

// =======================================================================
// depthwise conv 3x3 SAME + bias + silu for BOTH tensors
// =======================================================================
__global__ void __launch_bounds__(256) dwconv_k(const float* __restrict__ conv_w,
        const float* __restrict__ conv_b, const float* __restrict__ con_w,
        const float* __restrict__ con_b)
{
    __shared__ __align__(16) float imx[LL];
    __shared__ __align__(16) float imc[LL];
    int bd = blockIdx.x;
    int d  = bd % DI;
    const float* inx = g_xa_pre + (size_t)bd * LL;
    const float* inc = g_c_pre  + (size_t)bd * LL;
    float* outx = g_xa_conv + (size_t)bd * LL;
    float* outs = g_s       + (size_t)bd * LL;
    const float* wxp = conv_w + d * 9;
    const float* wcp = con_w  + d * 9;
    float bx = conv_b[d], bc = con_b[d];

    #pragma unroll
    for (int i = 0; i < 4; i++) {
        *(float4*)&imx[(threadIdx.x + 256*i)*4] = *(const float4*)&inx[(threadIdx.x + 256*i)*4];
        *(float4*)&imc[(threadIdx.x + 256*i)*4] = *(const float4*)&inc[(threadIdx.x + 256*i)*4];
    }
    float wx[9], wc[9];
    #pragma unroll
    for (int i = 0; i < 9; i++) { wx[i] = wxp[i]; wc[i] = wcp[i]; }
    __syncthreads();

    #pragma unroll
    for (int i = 0; i < 16; i++) {
        int l = threadIdx.x + 256*i;
        int y = l >> 6, x = l & 63;
        bool yl = y > 0, yh = y < 63, xl = x > 0, xh = x < 63;
        float ax = bx, ac = bc;
        if (yl) {
            if (xl) { ax = fmaf(imx[l-65], wx[0], ax); ac = fmaf(imc[l-65], wc[0], ac); }
            ax = fmaf(imx[l-64], wx[1], ax); ac = fmaf(imc[l-64], wc[1], ac);
            if (xh) { ax = fmaf(imx[l-63], wx[2], ax); ac = fmaf(imc[l-63], wc[2], ac); }
        }
        if (xl) { ax = fmaf(imx[l-1], wx[3], ax); ac = fmaf(imc[l-1], wc[3], ac); }
        ax = fmaf(imx[l], wx[4], ax); ac = fmaf(imc[l], wc[4], ac);
        if (xh) { ax = fmaf(imx[l+1], wx[5], ax); ac = fmaf(imc[l+1], wc[5], ac); }
        if (yh) {
            if (xl) { ax = fmaf(imx[l+63], wx[6], ax); ac = fmaf(imc[l+63], wc[6], ac); }
            ax = fmaf(imx[l+64], wx[7], ax); ac = fmaf(imc[l+64], wc[7], ac);
            if (xh) { ax = fmaf(imx[l+65], wx[8], ax); ac = fmaf(imc[l+65], wc[8], ac); }
        }
        float sa = silu_f(ax);
        outx[l] = sa;
        outs[l] = sa + silu_f(ac);
    }
}

// =======================================================================
// proj: 64 px/block; 3-stage cp.async stage 1; 3-stage cp.async stage 2.
// =======================================================================
__global__ void __launch_bounds__(256) proj_k(const float* __restrict__ x_proj_w,
        const float* __restrict__ dt_proj_w, const float* __restrict__ dt_proj_b,
        const int* __restrict__ rev_scan)
{
    __shared__ float xd[64*49];
    __shared__ __align__(16) union {
        struct { float sS[3][16*68]; float sB[3][16*48]; } a;
        float xaT[3][32*68];
    } u;

    int tid = threadIdx.x;
    int b   = blockIdx.x >> 6;
    int l0  = (blockIdx.x & 63) * 64;

    for (int e = tid; e < 3*16*48; e += 256) (&u.a.sB[0][0])[e] = 0.f;

    unsigned sS_b = (unsigned)__cvta_generic_to_shared(&u.a.sS[0][0]);
    unsigned sB_b = (unsigned)__cvta_generic_to_shared(&u.a.sB[0][0]);
    unsigned xa_b = (unsigned)__cvta_generic_to_shared(&u.xaT[0][0]);

    #define S1_PREFETCH(kc, bf)                                                \
    {                                                                          \
        int k = tid >> 4, px4 = tid & 15;                                      \
        cpa16(sS_b + (unsigned)(((bf)*16*68 + k*68 + px4*4)*4),                \
              g_s + ((size_t)(b*DI + (kc)*16 + k))*LL + l0 + px4*4);           \
        _Pragma("unroll")                                                      \
        for (int i = 0; i < 3; i++) {                                          \
            int e = tid + 256*i;                                               \
            int cc = e >> 4, kk = e & 15;                                      \
            if (cc < DR + 2*DS)                                                \
                cpa4(sB_b + (unsigned)(((bf)*16*48 + kk*48 + cc)*4),           \
                     x_proj_w + (size_t)cc*DI + (kc)*16 + kk);                 \
        }                                                                      \
    }
    #define S2_PREFETCH(cc, bf)                                                \
    {                                                                          \
        _Pragma("unroll")                                                      \
        for (int i = 0; i < 2; i++) {                                          \
            int e = tid + 256*i;                                               \
            int dd = e >> 4, px4 = e & 15;                                     \
            cpa16(xa_b + (unsigned)(((bf)*32*68 + dd*68 + px4*4)*4),           \
                  g_xa_conv + ((size_t)(b*DI + (cc)*32 + dd))*LL + l0 + px4*4);\
        }                                                                      \
    }

    __syncthreads();

    S1_PREFETCH(0, 0); cp_commit();
    S1_PREFETCH(1, 1); cp_commit();

    int tm = tid & 15, tn = tid >> 4;
    float acc[4][3];
    #pragma unroll
    for (int i = 0; i < 4; i++)
        #pragma unroll
        for (int j = 0; j < 3; j++) acc[i][j] = 0.f;

    const int NC1 = DI/16;
    for (int kc = 0; kc < NC1; kc++) {
        if (kc < NC1-1) cp_wait1(); else cp_wait0();
        __syncthreads();
        if (kc + 2 < NC1) { S1_PREFETCH(kc+2, (kc+2)%3); cp_commit(); }
        const float* sS = u.a.sS[kc%3];
        const float* sB = u.a.sB[kc%3];
        #pragma unroll
        for (int k = 0; k < 16; k++) {
            float4 av = *(const float4*)&sS[k*68 + tm*4];
            float b0 = sB[k*48 + tn*3 + 0];
            float b1 = sB[k*48 + tn*3 + 1];
            float b2 = sB[k*48 + tn*3 + 2];
            float ar[4] = {av.x, av.y, av.z, av.w};
            #pragma unroll
            for (int i = 0; i < 4; i++) {
                acc[i][0] = fmaf(ar[i], b0, acc[i][0]);
                acc[i][1] = fmaf(ar[i], b1, acc[i][1]);
                acc[i][2] = fmaf(ar[i], b2, acc[i][2]);
            }
        }
    }
    #pragma unroll
    for (int i = 0; i < 4; i++)
        #pragma unroll
        for (int j = 0; j < 3; j++)
            xd[(tm*4+i)*49 + tn*3+j] = acc[i][j];
    __syncthreads();

    S2_PREFETCH(0, 0); cp_commit();
    S2_PREFETCH(1, 1); cp_commit();

    int w = tid >> 5, lane = tid & 31;

    #pragma unroll
    for (int p = 0; p < 4; p++) {
        int px = w*8 + p*2 + (lane >> 4);
        int n  = lane & 15;
        int j  = __ldg(&rev_scan[l0 + px]);
        g_bc[((size_t)b*LL + j)*DS + n] =
            make_float2(xd[px*49 + DR + n], xd[px*49 + DR + DS + n]);
    }

    const int NC2 = DI/32;
    for (int c32 = 0; c32 < NC2; c32++) {
        if (c32 < NC2-1) cp_wait1(); else cp_wait0();
        __syncthreads();
        if (c32 + 2 < NC2) { S2_PREFETCH(c32+2, (c32+2)%3); cp_commit(); }
        int d = c32*32 + lane;
        float wr[DR];
        #pragma unroll
        for (int r = 0; r < DR; r++) wr[r] = __ldg(&dt_proj_w[(size_t)d*DR + r]);
        float bias = __ldg(&dt_proj_b[d]);
        const float* xaT = u.xaT[c32%3];
        #pragma unroll
        for (int p = 0; p < 8; p++) {
            int px = p*8 + w;
            float a = bias;
            #pragma unroll
            for (int r = 0; r < DR; r++) a = fmaf(wr[r], xd[px*49 + r], a);
            float delta = (a > 20.f) ? a : log1pf(__expf(a));
            float uval  = xaT[lane*68 + px];
            int j = __ldg(&rev_scan[l0 + px]);
            g_du[((size_t)b*LL + j)*DI + d] = make_float2(delta, uval);
        }
    }
    #undef S1_PREFETCH
    #undef S2_PREFETCH
}

// =======================================================================
// scan pass 1: per-chunk end-state from h=0 (no outputs).
// grid = 96 groups x (CH-1) chunks, block = 128 thr (8 channels x 16 states)
// =======================================================================
__global__ void __launch_bounds__(128) scan_p1_k(const float* __restrict__ A_logs)
{
    __shared__ __align__(16) float2 du2[3][TSTEP][8];
    __shared__ __align__(16) float2 bc2[3][TSTEP][DS];

    int blk = blockIdx.x;
    int k  = blk % (CH-1);
    int cb = blk / (CH-1);
    int b  = cb / 48;
    int d0 = (cb % 48) * 8;
    int tid = threadIdx.x;
    int wid = tid >> 5, lane = tid & 31;
    int g = lane >> 4, n = lane & 15;
    int ch = wid*2 + g;
    int d = d0 + ch;

    float a_coef = -__expf(A_logs[d*DS + n]);

    unsigned du_sm = (unsigned)__cvta_generic_to_shared(&du2[0][0][0]);
    unsigned bc_sm = (unsigned)__cvta_generic_to_shared(&bc2[0][0][0]);
    const float2* du_g = g_du + ((size_t)b*LL + k*CL)*DI + d0;
    const float2* bc_g = g_bc + ((size_t)b*LL + k*CL)*DS;

    #define P1_PRE(T, bf)                                                      \
    {                                                                          \
        _Pragma("unroll")                                                      \
        for (int i = 0; i < 2; i++) {                                          \
            int e = tid + 128*i;                                               \
            int jj = e >> 3, c = e & 7;                                        \
            cpa8(du_sm + (unsigned)((((bf)*TSTEP + jj)*8 + c)*8),              \
                 du_g + (size_t)((T)*TSTEP + jj)*DI + c);                      \
        }                                                                      \
        _Pragma("unroll")                                                      \
        for (int i = 0; i < 2; i++) {                                          \
            int e = tid + 128*i;                                               \
            int jj = e >> 3, q = e & 7;                                        \
            cpa16(bc_sm + (unsigned)((((bf)*TSTEP + jj)*DS + q*2)*8),          \
                  bc_g + (size_t)((T)*TSTEP + jj)*DS + q*2);                   \
        }                                                                      \
    }

    P1_PRE(0, 0); cp_commit();
    P1_PRE(1, 1); cp_commit();

    float h = 0.f, Ssum = 0.f;
    for (int T = 0; T < PTILES; T++) {
        if (T < PTILES-1) cp_wait1(); else cp_wait0();
        __syncthreads();
        if (T + 2 < PTILES) { P1_PRE(T+2, (T+2)%3); cp_commit(); }
        int bf = T % 3;
        #pragma unroll
        for (int jj = 0; jj < TSTEP; jj++) {
            float2 du = du2[bf][jj][ch];
            float2 bc = bc2[bf][jj][n];
            float dA = __expf(du.x * a_coef);
            h = fmaf(dA, h, du.x * du.y * bc.x);
            Ssum += du.x;
        }
    }
    #undef P1_PRE

    g_E[((size_t)(b*CH + k)*DI + d)*DS + n] = h;
    if (n == 0) g_Ssum[(size_t)(b*CH + k)*DI + d] = Ssum;
}

// =======================================================================
// scan pass 2: compose chunk carries.  1 thread per (b,d,n).
// =======================================================================
__global__ void __launch_bounds__(256) scan_p2_k(const float* __restrict__ A_logs)
{
    int t = blockIdx.x * 256 + threadIdx.x;    // 0 .. BB*DI*DS-1
    int n  = t & 15;
    int dd = (t >> 4) % DI;
    int b  = t / (DI*DS);
    float a_coef = -__expf(A_logs[dd*DS + n]);
    float H = 0.f;
    for (int k = 0; k < CH; k++) {
        g_hin[((size_t)(b*CH + k)*DI + dd)*DS + n] = H;
        if (k < CH-1) {
            float S = g_Ssum[(size_t)(b*CH + k)*DI + dd];
            float E = g_E[((size_t)(b*CH + k)*DI + dd)*DS + n];
            H = fmaf(__expf(a_coef * S), H, E);
        }
    }
}

// =======================================================================
// scan pass 3: full scan within chunk, seeded with carry, outputs y.
// grid = 96 groups x CH chunks
// =======================================================================
__global__ void __launch_bounds__(128) scan_p3_k(const float* __restrict__ A_logs,
        const float* __restrict__ Ds, const int* __restrict__ scan_path)
{
    __shared__ __align__(16) float2 du2[2][TSTEP][8];
    __shared__ __align__(16) float2 bc2[2][TSTEP][DS];
    __shared__ float  ps[TSTEP*8*17];
    __shared__ float  s_D[8];

    int blk = blockIdx.x;
    int k  = blk % CH;
    int cb = blk / CH;
    int b  = cb / 48;
    int d0 = (cb % 48) * 8;
    int tid = threadIdx.x;
    int wid = tid >> 5, lane = tid & 31;
    int g = lane >> 4, n = lane & 15;
    int ch = wid*2 + g;
    int d = d0 + ch;

    float a_coef = -__expf(A_logs[d*DS + n]);
    if (tid < 8) s_D[tid] = Ds[d0 + tid];

    unsigned du_sm = (unsigned)__cvta_generic_to_shared(&du2[0][0][0]);
    unsigned bc_sm = (unsigned)__cvta_generic_to_shared(&bc2[0][0][0]);
    const float2* du_g = g_du + ((size_t)b*LL + k*CL)*DI + d0;
    const float2* bc_g = g_bc + ((size_t)b*LL + k*CL)*DS;

    {
        #pragma unroll
        for (int i = 0; i < 2; i++) {
            int e = tid + 128*i;
            int jj = e >> 3, c = e & 7;
            cpa8(du_sm + (unsigned)((jj*8 + c)*8), du_g + (size_t)jj*DI + c);
        }
        #pragma unroll
        for (int i = 0; i < 2; i++) {
            int e = tid + 128*i;
            int jj = e >> 3, q = e & 7;
            cpa16(bc_sm + (unsigned)((jj*DS + q*2)*8), bc_g + (size_t)jj*DS + q*2);
        }
        cp_commit();
    }

    float h = g_hin[((size_t)(b*CH + k)*DI + d)*DS + n];
    int buf = 0;
    for (int T = 0; T < PTILES; T++) {
        if (T + 1 < PTILES) {
            int o = (buf^1) * TSTEP;
            #pragma unroll
            for (int i = 0; i < 2; i++) {
                int e = tid + 128*i;
                int jj = e >> 3, c = e & 7;
                cpa8(du_sm + (unsigned)(((o+jj)*8 + c)*8),
                     du_g + (size_t)((T+1)*TSTEP + jj)*DI + c);
            }
            #pragma unroll
            for (int i = 0; i < 2; i++) {
                int e = tid + 128*i;
                int jj = e >> 3, q = e & 7;
                cpa16(bc_sm + (unsigned)(((o+jj)*DS + q*2)*8),
                      bc_g + (size_t)((T+1)*TSTEP + jj)*DS + q*2);
            }
            cp_commit();
            cp_wait1();
        } else {
            cp_wait0();
        }
        __syncthreads();

        #pragma unroll 8
        for (int jj = 0; jj < TSTEP; jj++) {
            float2 du = du2[buf][jj][ch];
            float2 bc = bc2[buf][jj][n];
            float dA = __expf(du.x * a_coef);
            h = fmaf(dA, h, du.x * du.y * bc.x);
            ps[(jj*8 + ch)*17 + n] = h * bc.y;
        }
        __syncthreads();

        #pragma unroll
        for (int i = 0; i < 2; i++) {
            int e = tid + 128*i;
            int jj = e >> 3, c = e & 7;
            const float* p = &ps[(jj*8 + c)*17];
            float sum = p[0];
            #pragma unroll
            for (int kk = 1; kk < DS; kk++) sum += p[kk];
            float uval = du2[buf][jj][c].y;
            int pos = __ldg(&scan_path[k*CL + T*TSTEP + jj]);
            g_y[((size_t)b*LL + pos)*DI + d0 + c] = fmaf(uval, s_D[c], sum);
        }
        buf ^= 1;
    }
}

// ---------------- launch ----------------
extern "C" void kernel_launch(void* const* d_in, const int* in_sizes, int n_in,
                              void* d_out, int out_size)
{
    const float* x          = (const float*)d_in[0];
    const float* cond       = (const float*)d_in[1];
    const float* W_in       = (const float*)d_in[2];
    const float* W_con      = (const float*)d_in[3];
    const float* conv_w     = (const float*)d_in[4];
    const float* conv_b     = (const float*)d_in[5];
    const float* con_conv_w = (const float*)d_in[6];
    const float* con_conv_b = (const float*)d_in[7];
    const float* x_proj_w   = (const float*)d_in[8];
    const float* dt_proj_w  = (const float*)d_in[9];
    const float* dt_proj_b  = (const float*)d_in[10];
    const float* A_logs     = (const float*)d_in[11];
    const float* Ds         = (const float*)d_in[12];
    const float* ln_w       = (const float*)d_in[13];
    const float* ln_b       = (const float*)d_in[14];
    const float* W_out      = (const float*)d_in[15];
    const int*   scan_path  = (const int*)d_in[16];
    const int*   rev_scan   = (const int*)d_in[17];
    float* out = (float*)d_out;

    gemm_in_k<<<dim3(3*DI/64, NROWS/128), 256>>>(x, cond, W_in, W_con);
    dwconv_k<<<BB*DI, 256>>>(conv_w, conv_b, con_conv_w, con_conv_b);
    proj_k<<<NROWS/64, 256>>>(x_proj_w, dt_proj_w, dt_proj_b, rev_scan);
    scan_p1_k<<<96*(CH-1), 128>>>(A_logs);
    scan_p2_k<<<(BB*DI*DS)/256, 256>>>(A_logs);
    scan_p3_k<<<96*CH, 128>>>(A_logs, Ds, scan_path);
    ln_stats_k<<<NROWS/8, 256>>>();
    gemm_out_k<<<dim3(DM/64, NROWS/128), 256>>>(W_out, ln_w, ln_b, out);
}

// round 9
// speedup vs baseline: 1.7733x; 1.0200x over previous
#include <cuda_runtime.h>

#define BB 2
#define DM 192
#define DI 384
#define DS 16
#define DR 12
#define HH 64
#define WW 64
#define LL 4096
#define NROWS (BB*LL)   // 8192

#define TSTEP 32
#define CH 32
#define CL (LL/CH)          // 128 steps per chunk
#define PTILES (CL/TSTEP)   // 4 tiles per chunk

// ---------------- scratch ----------------
__device__ float  g_xa_pre[BB*DI*LL];
__device__ float  g_c_pre [BB*DI*LL];
__device__ float  g_xa_conv[BB*DI*LL];
__device__ float  g_s     [BB*DI*LL];
__device__ float  g_z     [NROWS*DI];
__device__ float2 g_du    [BB*LL*DI];
__device__ float2 g_bc    [BB*LL*DS];
__device__ float  g_y     [NROWS*DI];
__device__ float2 g_stats [NROWS];
__device__ float  g_xd    [NROWS*48];      // x_dbl per pixel (spatial order)
__device__ float  g_E     [BB*CH*DI*DS];
__device__ float  g_Ssum  [BB*CH*DI];
__device__ float  g_hin   [BB*CH*DI*DS];

__device__ __forceinline__ float silu_f(float v){ return v / (1.f + __expf(-v)); }

__device__ __forceinline__ void cpa4(unsigned dst, const void* src){
    asm volatile("cp.async.ca.shared.global [%0], [%1], 4;\n" :: "r"(dst), "l"(src));
}
__device__ __forceinline__ void cpa8(unsigned dst, const void* src){
    asm volatile("cp.async.ca.shared.global [%0], [%1], 8;\n" :: "r"(dst), "l"(src));
}
__device__ __forceinline__ void cpa16(unsigned dst, const void* src){
    asm volatile("cp.async.ca.shared.global [%0], [%1], 16;\n" :: "r"(dst), "l"(src));
}
__device__ __forceinline__ void cp_commit(){ asm volatile("cp.async.commit_group;\n"); }
__device__ __forceinline__ void cp_wait1(){ asm volatile("cp.async.wait_group 1;\n"); }
__device__ __forceinline__ void cp_wait0(){ asm volatile("cp.async.wait_group 0;\n"); }

// ---- packed fp32x2 helpers ----
__device__ __forceinline__ unsigned long long pk2(float lo, float hi){
    unsigned long long r;
    asm("mov.b64 %0, {%1, %2};" : "=l"(r) : "f"(lo), "f"(hi));
    return r;
}
__device__ __forceinline__ void upk2(unsigned long long v, float& lo, float& hi){
    asm("mov.b64 {%0, %1}, %2;" : "=f"(lo), "=f"(hi) : "l"(v));
}
__device__ __forceinline__ void ffma2(unsigned long long& d,
        unsigned long long a, unsigned long long b){
    asm("fma.rn.f32x2 %0, %1, %2, %0;" : "+l"(d) : "l"(a), "l"(b));
}

#define AS_STRIDE 132
#define BS_STRIDE 68

// =======================================================================
// gemm_in: BOTH input GEMMs, 128x64 tile, 8x4 micro, f32x2 inner loop.
// =======================================================================
__global__ void __launch_bounds__(256) gemm_in_k(const float* __restrict__ x,
        const float* __restrict__ cond, const float* __restrict__ W_in,
        const float* __restrict__ W_con)
{
    __shared__ __align__(16) union {
        struct { float As[2][16*AS_STRIDE]; float Bs[2][16*BS_STRIDE]; } s;
        float Ts[64*129];
    } u;

    const int K = DM;
    int tid = threadIdx.x;
    int tx = tid & 15, ty = tid >> 4;
    int n0 = blockIdx.x * 64;
    int m0 = blockIdx.y * 128;
    bool is_c = (n0 >= 2*DI);
    const float* A  = is_c ? cond  : x;
    const float* Bw = is_c ? W_con : W_in;
    int nb = is_c ? n0 - 2*DI : n0;

    int am  = tid >> 1;
    int akq = (tid & 1) * 8;
    int bn  = tid >> 2;
    int bkq = (tid & 3) * 4;
    const float* aP = A  + (size_t)(m0 + am) * K + akq;
    const float* bP = Bw + (size_t)(nb + bn) * K + bkq;

    unsigned long long acc2[4][4];
    #pragma unroll
    for (int i = 0; i < 4; i++)
        #pragma unroll
        for (int j = 0; j < 4; j++) acc2[i][j] = 0ULL;

    {
        float4 a0 = *(const float4*)(aP);
        float4 a1 = *(const float4*)(aP + 4);
        float4 b0 = *(const float4*)(bP);
        float* As = u.s.As[0]; float* Bs = u.s.Bs[0];
        As[(akq+0)*AS_STRIDE+am]=a0.x; As[(akq+1)*AS_STRIDE+am]=a0.y;
        As[(akq+2)*AS_STRIDE+am]=a0.z; As[(akq+3)*AS_STRIDE+am]=a0.w;
        As[(akq+4)*AS_STRIDE+am]=a1.x; As[(akq+5)*AS_STRIDE+am]=a1.y;
        As[(akq+6)*AS_STRIDE+am]=a1.z; As[(akq+7)*AS_STRIDE+am]=a1.w;
        Bs[(bkq+0)*BS_STRIDE+bn]=b0.x; Bs[(bkq+1)*BS_STRIDE+bn]=b0.y;
        Bs[(bkq+2)*BS_STRIDE+bn]=b0.z; Bs[(bkq+3)*BS_STRIDE+bn]=b0.w;
    }

    int buf = 0;
    const int nch = K / 16;
    for (int c = 0; c < nch; c++) {
        float4 na0, na1, nb0;
        if (c + 1 < nch) {
            na0 = *(const float4*)(aP + (c+1)*16);
            na1 = *(const float4*)(aP + (c+1)*16 + 4);
            nb0 = *(const float4*)(bP + (c+1)*16);
        }
        __syncthreads();
        const float* As = u.s.As[buf];
        const float* Bs = u.s.Bs[buf];
        #pragma unroll
        for (int kk = 0; kk < 16; kk++) {
            float4 a0 = *(const float4*)&As[kk*AS_STRIDE + ty*8];
            float4 a1 = *(const float4*)&As[kk*AS_STRIDE + ty*8 + 4];
            float4 b0 = *(const float4*)&Bs[kk*BS_STRIDE + tx*4];
            unsigned long long ap[4] = {
                pk2(a0.x, a0.y), pk2(a0.z, a0.w),
                pk2(a1.x, a1.y), pk2(a1.z, a1.w) };
            unsigned long long bd[4] = {
                pk2(b0.x, b0.x), pk2(b0.y, b0.y),
                pk2(b0.z, b0.z), pk2(b0.w, b0.w) };
            #pragma unroll
            for (int ip = 0; ip < 4; ip++)
                #pragma unroll
                for (int j = 0; j < 4; j++)
                    ffma2(acc2[ip][j], ap[ip], bd[j]);
        }
        if (c + 1 < nch) {
            float* Asw = u.s.As[buf^1]; float* Bsw = u.s.Bs[buf^1];
            Asw[(akq+0)*AS_STRIDE+am]=na0.x; Asw[(akq+1)*AS_STRIDE+am]=na0.y;
            Asw[(akq+2)*AS_STRIDE+am]=na0.z; Asw[(akq+3)*AS_STRIDE+am]=na0.w;
            Asw[(akq+4)*AS_STRIDE+am]=na1.x; Asw[(akq+5)*AS_STRIDE+am]=na1.y;
            Asw[(akq+6)*AS_STRIDE+am]=na1.z; Asw[(akq+7)*AS_STRIDE+am]=na1.w;
            Bsw[(bkq+0)*BS_STRIDE+bn]=nb0.x; Bsw[(bkq+1)*BS_STRIDE+bn]=nb0.y;
            Bsw[(bkq+2)*BS_STRIDE+bn]=nb0.z; Bsw[(bkq+3)*BS_STRIDE+bn]=nb0.w;
            buf ^= 1;
        }
    }

    float acc[8][4];
    #pragma unroll
    for (int ip = 0; ip < 4; ip++)
        #pragma unroll
        for (int j = 0; j < 4; j++)
            upk2(acc2[ip][j], acc[2*ip][j], acc[2*ip+1][j]);

    bool transp = is_c || (n0 < DI);
    if (transp) {
        __syncthreads();
        #pragma unroll
        for (int i = 0; i < 8; i++)
            #pragma unroll
            for (int j = 0; j < 4; j++)
                u.Ts[(tx*4+j)*129 + ty*8+i] = acc[i][j];
        __syncthreads();
        int b = m0 >> 12, l0 = m0 & 4095;
        float* dst = is_c ? g_c_pre : g_xa_pre;
        for (int e = tid; e < 64*128; e += 256) {
            int row = e >> 7, cc = e & 127;
            dst[((size_t)(b*DI + nb + row))*LL + l0 + cc] = u.Ts[row*129 + cc];
        }
    } else {
        #pragma unroll
        for (int i = 0; i < 8; i++) {
            int m = m0 + ty*8 + i;
            #pragma unroll
            for (int j = 0; j < 4; j++) {
                int nz = n0 - DI + tx*4 + j;
                g_z[(size_t)m*DI + nz] = silu_f(acc[i][j]);
            }
        }
    }
}

// =======================================================================
// gemm_out: out = LN(y)*z @ W_out^T (scalar FFMA - control)
// =======================================================================
__global__ void __launch_bounds__(256) gemm_out_k(const float* __restrict__ Bw,
        const float* __restrict__ ln_w, const float* __restrict__ ln_b,
        float* __restrict__ out)
{
    __shared__ __align__(16) float As[2][16*AS_STRIDE];
    __shared__ __align__(16) float Bs[2][16*BS_STRIDE];

    const int K = DI, N = DM;
    int tid = threadIdx.x;
    int tx = tid & 15, ty = tid >> 4;
    int n0 = blockIdx.x * 64;
    int m0 = blockIdx.y * 128;

    int am  = tid >> 1;
    int akq = (tid & 1) * 8;
    int bn  = tid >> 2;
    int bkq = (tid & 3) * 4;
    const float* yP = g_y + (size_t)(m0 + am) * K + akq;
    const float* zP = g_z + (size_t)(m0 + am) * K + akq;
    const float* bP = Bw  + (size_t)(n0 + bn) * K + bkq;
    float2 st = g_stats[m0 + am];

    float acc[8][4];
    #pragma unroll
    for (int i = 0; i < 8; i++)
        #pragma unroll
        for (int j = 0; j < 4; j++) acc[i][j] = 0.f;

    #define LOADA(c, r0, r1)                                                   \
    {                                                                          \
        int k = (c)*16;                                                        \
        float4 y0 = *(const float4*)(yP + k);                                  \
        float4 y1 = *(const float4*)(yP + k + 4);                              \
        float4 z0 = *(const float4*)(zP + k);                                  \
        float4 z1 = *(const float4*)(zP + k + 4);                              \
        float4 w0 = *(const float4*)(ln_w + k + akq);                          \
        float4 w1 = *(const float4*)(ln_w + k + akq + 4);                      \
        float4 lb0 = *(const float4*)(ln_b + k + akq);                         \
        float4 lb1 = *(const float4*)(ln_b + k + akq + 4);                     \
        r0.x = ((y0.x-st.x)*st.y*w0.x + lb0.x)*z0.x;                           \
        r0.y = ((y0.y-st.x)*st.y*w0.y + lb0.y)*z0.y;                           \
        r0.z = ((y0.z-st.x)*st.y*w0.z + lb0.z)*z0.z;                           \
        r0.w = ((y0.w-st.x)*st.y*w0.w + lb0.w)*z0.w;                           \
        r1.x = ((y1.x-st.x)*st.y*w1.x + lb1.x)*z1.x;                           \
        r1.y = ((y1.y-st.x)*st.y*w1.y + lb1.y)*z1.y;                           \
        r1.z = ((y1.z-st.x)*st.y*w1.z + lb1.z)*z1.z;                           \
        r1.w = ((y1.w-st.x)*st.y*w1.w + lb1.w)*z1.w;                           \
    }

    {
        float4 a0, a1;
        LOADA(0, a0, a1);
        float4 b0 = *(const float4*)(bP);
        As[0][(akq+0)*AS_STRIDE+am]=a0.x; As[0][(akq+1)*AS_STRIDE+am]=a0.y;
        As[0][(akq+2)*AS_STRIDE+am]=a0.z; As[0][(akq+3)*AS_STRIDE+am]=a0.w;
        As[0][(akq+4)*AS_STRIDE+am]=a1.x; As[0][(akq+5)*AS_STRIDE+am]=a1.y;
        As[0][(akq+6)*AS_STRIDE+am]=a1.z; As[0][(akq+7)*AS_STRIDE+am]=a1.w;
        Bs[0][(bkq+0)*BS_STRIDE+bn]=b0.x; Bs[0][(bkq+1)*BS_STRIDE+bn]=b0.y;
        Bs[0][(bkq+2)*BS_STRIDE+bn]=b0.z; Bs[0][(bkq+3)*BS_STRIDE+bn]=b0.w;
    }

    int buf = 0;
    const int nch = K / 16;
    for (int c = 0; c < nch; c++) {
        float4 na0, na1, nb0;
        if (c + 1 < nch) {
            LOADA(c+1, na0, na1);
            nb0 = *(const float4*)(bP + (c+1)*16);
        }
        __syncthreads();
        const float* Asr = As[buf];
        const float* Bsr = Bs[buf];
        #pragma unroll
        for (int kk = 0; kk < 16; kk++) {
            float4 a0 = *(const float4*)&Asr[kk*AS_STRIDE + ty*8];
            float4 a1 = *(const float4*)&Asr[kk*AS_STRIDE + ty*8 + 4];
            float4 b0 = *(const float4*)&Bsr[kk*BS_STRIDE + tx*4];
            float ar[8] = {a0.x,a0.y,a0.z,a0.w,a1.x,a1.y,a1.z,a1.w};
            float br[4] = {b0.x,b0.y,b0.z,b0.w};
            #pragma unroll
            for (int i = 0; i < 8; i++)
                #pragma unroll
                for (int j = 0; j < 4; j++)
                    acc[i][j] = fmaf(ar[i], br[j], acc[i][j]);
        }
        if (c + 1 < nch) {
            float* Asw = As[buf^1]; float* Bsw = Bs[buf^1];
            Asw[(akq+0)*AS_STRIDE+am]=na0.x; Asw[(akq+1)*AS_STRIDE+am]=na0.y;
            Asw[(akq+2)*AS_STRIDE+am]=na0.z; Asw[(akq+3)*AS_STRIDE+am]=na0.w;
            Asw[(akq+4)*AS_STRIDE+am]=na1.x; Asw[(akq+5)*AS_STRIDE+am]=na1.y;
            Asw[(akq+6)*AS_STRIDE+am]=na1.z; Asw[(akq+7)*AS_STRIDE+am]=na1.w;
            Bsw[(bkq+0)*BS_STRIDE+bn]=nb0.x; Bsw[(bkq+1)*BS_STRIDE+bn]=nb0.y;
            Bsw[(bkq+2)*BS_STRIDE+bn]=nb0.z; Bsw[(bkq+3)*BS_STRIDE+bn]=nb0.w;
            buf ^= 1;
        }
    }
    #undef LOADA

    #pragma unroll
    for (int i = 0; i < 8; i++) {
        int m = m0 + ty*8 + i;
        #pragma unroll
        for (int j = 0; j < 4; j++) {
            int n = n0 + tx*4 + j;
            out[(size_t)m*N + n] = acc[i][j];
        }
    }
}

// =======================================================================
// per-row LN stats
// =======================================================================
__global__ void __launch_bounds__(256) ln_stats_k()
{
    int row = blockIdx.x * 8 + (threadIdx.x >> 5);
    int lane = threadIdx.x & 31;
    const float* yr = g_y + (size_t)row * DI;
    float s = 0.f, q = 0.f;
    #pragma unroll
    for (int i = 0; i < 12; i++) {
        float v = yr[lane + 32*i];
        s += v; q += v*v;
    }
    #pragma unroll
    for (int o = 16; o > 0; o >>= 1) {
        s += __shfl_xor_sync(0xFFFFFFFFu, s, o);
        q += __shfl_xor_sync(0xFFFFFFFFu, q, o);
    }
    if (lane == 0) {
        float mu = s * (1.f / DI);
        float var = q * (1.f / DI) - mu*mu;
        g_stats[row] = make_float2(mu, rsqrtf(var + 1e-5f));
    }
}

// =======================================================================
// depthwise conv 3x3 + bias + silu for BOTH tensors
// =======================================================================
__global__ void __launch_bounds__(256) dwconv_k(const float* __restrict__ conv_w,
        const float* __restrict__ conv_b, const float* __restrict__ con_w,
        const float* __restrict__ con_b)
{
    __shared__ __align__(16) float imx[LL];
    __shared__ __align__(16) float imc[LL];
    int bd = blockIdx.x;
    int d  = bd % DI;
    const float* inx = g_xa_pre + (size_t)bd * LL;
    const float* inc = g_c_pre  + (size_t)bd * LL;
    float* outx = g_xa_conv + (size_t)bd * LL;
    float* outs = g_s       + (size_t)bd * LL;
    const float* wxp = conv_w + d * 9;
    const float* wcp = con_w  + d * 9;
    float bx = conv_b[d], bc = con_b[d];

    #pragma unroll
    for (int i = 0; i < 4; i++) {
        *(float4*)&imx[(threadIdx.x + 256*i)*4] = *(const float4*)&inx[(threadIdx.x + 256*i)*4];
        *(float4*)&imc[(threadIdx.x + 256*i)*4] = *(const float4*)&inc[(threadIdx.x + 256*i)*4];
    }
    float wx[9], wc[9];
    #pragma unroll
    for (int i = 0; i < 9; i++) { wx[i] = wxp[i]; wc[i] = wcp[i]; }
    __syncthreads();

    #pragma unroll
    for (int i = 0; i < 16; i++) {
        int l = threadIdx.x + 256*i;
        int y = l >> 6, x = l & 63;
        bool yl = y > 0, yh = y < 63, xl = x > 0, xh = x < 63;
        float ax = bx, ac = bc;
        if (yl) {
            if (xl) { ax = fmaf(imx[l-65], wx[0], ax); ac = fmaf(imc[l-65], wc[0], ac); }
            ax = fmaf(imx[l-64], wx[1], ax); ac = fmaf(imc[l-64], wc[1], ac);
            if (xh) { ax = fmaf(imx[l-63], wx[2], ax); ac = fmaf(imc[l-63], wc[2], ac); }
        }
        if (xl) { ax = fmaf(imx[l-1], wx[3], ax); ac = fmaf(imc[l-1], wc[3], ac); }
        ax = fmaf(imx[l], wx[4], ax); ac = fmaf(imc[l], wc[4], ac);
        if (xh) { ax = fmaf(imx[l+1], wx[5], ax); ac = fmaf(imc[l+1], wc[5], ac); }
        if (yh) {
            if (xl) { ax = fmaf(imx[l+63], wx[6], ax); ac = fmaf(imc[l+63], wc[6], ac); }
            ax = fmaf(imx[l+64], wx[7], ax); ac = fmaf(imc[l+64], wc[7], ac);
            if (xh) { ax = fmaf(imx[l+65], wx[8], ax); ac = fmaf(imc[l+65], wc[8], ac); }
        }
        float sa = silu_f(ax);
        outx[l] = sa;
        outs[l] = sa + silu_f(ac);
    }
}

// =======================================================================
// proj1: 64 px/block, x_proj GEMM (3-stage cp.async), write xd + B/C.
// =======================================================================
__global__ void __launch_bounds__(256) proj1_k(const float* __restrict__ x_proj_w,
        const int* __restrict__ rev_scan)
{
    __shared__ float xd[64*49];
    __shared__ __align__(16) struct { float sS[3][16*68]; float sB[3][16*48]; } a;

    int tid = threadIdx.x;
    int b   = blockIdx.x >> 6;
    int l0  = (blockIdx.x & 63) * 64;

    for (int e = tid; e < 3*16*48; e += 256) (&a.sB[0][0])[e] = 0.f;

    unsigned sS_b = (unsigned)__cvta_generic_to_shared(&a.sS[0][0]);
    unsigned sB_b = (unsigned)__cvta_generic_to_shared(&a.sB[0][0]);

    #define S1_PREFETCH(kc, bf)                                                \
    {                                                                          \
        int k = tid >> 4, px4 = tid & 15;                                      \
        cpa16(sS_b + (unsigned)(((bf)*16*68 + k*68 + px4*4)*4),                \
              g_s + ((size_t)(b*DI + (kc)*16 + k))*LL + l0 + px4*4);           \
        _Pragma("unroll")                                                      \
        for (int i = 0; i < 3; i++) {                                          \
            int e = tid + 256*i;                                               \
            int cc = e >> 4, kk = e & 15;                                      \
            if (cc < DR + 2*DS)                                                \
                cpa4(sB_b + (unsigned)(((bf)*16*48 + kk*48 + cc)*4),           \
                     x_proj_w + (size_t)cc*DI + (kc)*16 + kk);                 \
        }                                                                      \
    }

    __syncthreads();

    S1_PREFETCH(0, 0); cp_commit();
    S1_PREFETCH(1, 1); cp_commit();

    int tm = tid & 15, tn = tid >> 4;
    float acc[4][3];
    #pragma unroll
    for (int i = 0; i < 4; i++)
        #pragma unroll
        for (int j = 0; j < 3; j++) acc[i][j] = 0.f;

    const int NC1 = DI/16;
    for (int kc = 0; kc < NC1; kc++) {
        if (kc < NC1-1) cp_wait1(); else cp_wait0();
        __syncthreads();
        if (kc + 2 < NC1) { S1_PREFETCH(kc+2, (kc+2)%3); cp_commit(); }
        const float* sS = a.sS[kc%3];
        const float* sB = a.sB[kc%3];
        #pragma unroll
        for (int k = 0; k < 16; k++) {
            float4 av = *(const float4*)&sS[k*68 + tm*4];
            float b0 = sB[k*48 + tn*3 + 0];
            float b1 = sB[k*48 + tn*3 + 1];
            float b2 = sB[k*48 + tn*3 + 2];
            float ar[4] = {av.x, av.y, av.z, av.w};
            #pragma unroll
            for (int i = 0; i < 4; i++) {
                acc[i][0] = fmaf(ar[i], b0, acc[i][0]);
                acc[i][1] = fmaf(ar[i], b1, acc[i][1]);
                acc[i][2] = fmaf(ar[i], b2, acc[i][2]);
            }
        }
    }
    #pragma unroll
    for (int i = 0; i < 4; i++)
        #pragma unroll
        for (int j = 0; j < 3; j++)
            xd[(tm*4+i)*49 + tn*3+j] = acc[i][j];
    __syncthreads();

    // write xd to gmem (coalesced-ish rows of 48)
    for (int e = tid; e < 64*48; e += 256) {
        int row = e / 48, cc = e % 48;
        g_xd[((size_t)(b*LL) + l0 + row)*48 + cc] = xd[row*49 + cc];
    }

    int w = tid >> 5, lane = tid & 31;
    #pragma unroll
    for (int p = 0; p < 4; p++) {
        int px = w*8 + p*2 + (lane >> 4);
        int n  = lane & 15;
        int j  = __ldg(&rev_scan[l0 + px]);
        g_bc[((size_t)b*LL + j)*DS + n] =
            make_float2(xd[px*49 + DR + n], xd[px*49 + DR + DS + n]);
    }
    #undef S1_PREFETCH
}

// =======================================================================
// proj2: dt_proj + softplus + (delta,u) scatter. 512 blocks.
// block = (b, l-tile of 32 px, d-half of 192)
// =======================================================================
__global__ void __launch_bounds__(256) proj2_k(const float* __restrict__ dt_proj_w,
        const float* __restrict__ dt_proj_b, const int* __restrict__ rev_scan)
{
    __shared__ float sxd[32*13];
    __shared__ __align__(16) float xaT[3][32*36];

    int blk = blockIdx.x;
    int dh = blk & 1;
    int lt = (blk >> 1) & 127;
    int b  = blk >> 8;
    int l0 = lt * 32;
    int d0h = dh * 192;
    int tid = threadIdx.x, w = tid >> 5, lane = tid & 31;

    unsigned xa_b = (unsigned)__cvta_generic_to_shared(&xaT[0][0]);

    #define P2_PRE(cc, bf)                                                     \
    {                                                                          \
        int dd = tid >> 3, px4 = tid & 7;                                      \
        cpa16(xa_b + (unsigned)(((bf)*32*36 + dd*36 + px4*4)*4),               \
              g_xa_conv + ((size_t)(b*DI + d0h + (cc)*32 + dd))*LL + l0 + px4*4); \
    }

    P2_PRE(0, 0); cp_commit();
    P2_PRE(1, 1); cp_commit();

    for (int e = tid; e < 32*12; e += 256) {
        int row = e / 12, r = e % 12;
        sxd[row*13 + r] = g_xd[((size_t)(b*LL) + l0 + row)*48 + r];
    }

    const int NC2 = 6;
    for (int c = 0; c < NC2; c++) {
        if (c < NC2-1) cp_wait1(); else cp_wait0();
        __syncthreads();
        if (c + 2 < NC2) { P2_PRE(c+2, (c+2)%3); cp_commit(); }
        int d = d0h + c*32 + lane;
        float wr[DR];
        #pragma unroll
        for (int r = 0; r < DR; r++) wr[r] = __ldg(&dt_proj_w[(size_t)d*DR + r]);
        float bias = __ldg(&dt_proj_b[d]);
        const float* xa = xaT[c%3];
        #pragma unroll
        for (int p = 0; p < 4; p++) {
            int px = w*4 + p;
            float aa = bias;
            #pragma unroll
            for (int r = 0; r < DR; r++) aa = fmaf(wr[r], sxd[px*13 + r], aa);
            float delta = (aa > 20.f) ? aa : log1pf(__expf(aa));
            float uval  = xa[lane*36 + px];
            int j = __ldg(&rev_scan[l0 + px]);
            g_du[((size_t)b*LL + j)*DI + d] = make_float2(delta, uval);
        }
    }
    #undef P2_PRE
}

// =======================================================================
// scan pass 1: per-chunk end-state from h=0.
// =======================================================================
__global__ void __launch_bounds__(128) scan_p1_k(const float* __restrict__ A_logs)
{
    __shared__ __align__(16) float2 du2[3][TSTEP][8];
    __shared__ __align__(16) float2 bc2[3][TSTEP][DS];

    int blk = blockIdx.x;
    int k  = blk % (CH-1);
    int cb = blk / (CH-1);
    int b  = cb / 48;
    int d0 = (cb % 48) * 8;
    int tid = threadIdx.x;
    int wid = tid >> 5, lane = tid & 31;
    int g = lane >> 4, n = lane & 15;
    int ch = wid*2 + g;
    int d = d0 + ch;

    float a_coef = -__expf(A_logs[d*DS + n]);

    unsigned du_sm = (unsigned)__cvta_generic_to_shared(&du2[0][0][0]);
    unsigned bc_sm = (unsigned)__cvta_generic_to_shared(&bc2[0][0][0]);
    const float2* du_g = g_du + ((size_t)b*LL + k*CL)*DI + d0;
    const float2* bc_g = g_bc + ((size_t)b*LL + k*CL)*DS;

    #define P1_PRE(T, bf)                                                      \
    {                                                                          \
        _Pragma("unroll")                                                      \
        for (int i = 0; i < 2; i++) {                                          \
            int e = tid + 128*i;                                               \
            int jj = e >> 3, c = e & 7;                                        \
            cpa8(du_sm + (unsigned)((((bf)*TSTEP + jj)*8 + c)*8),              \
                 du_g + (size_t)((T)*TSTEP + jj)*DI + c);                      \
        }                                                                      \
        _Pragma("unroll")                                                      \
        for (int i = 0; i < 2; i++) {                                          \
            int e = tid + 128*i;                                               \
            int jj = e >> 3, q = e & 7;                                        \
            cpa16(bc_sm + (unsigned)((((bf)*TSTEP + jj)*DS + q*2)*8),          \
                  bc_g + (size_t)((T)*TSTEP + jj)*DS + q*2);                   \
        }                                                                      \
    }

    P1_PRE(0, 0); cp_commit();
    P1_PRE(1, 1); cp_commit();

    float h = 0.f, Ssum = 0.f;
    for (int T = 0; T < PTILES; T++) {
        if (T < PTILES-1) cp_wait1(); else cp_wait0();
        __syncthreads();
        if (T + 2 < PTILES) { P1_PRE(T+2, (T+2)%3); cp_commit(); }
        int bf = T % 3;
        #pragma unroll
        for (int jj = 0; jj < TSTEP; jj++) {
            float2 du = du2[bf][jj][ch];
            float2 bc = bc2[bf][jj][n];
            float dA = __expf(du.x * a_coef);
            h = fmaf(dA, h, du.x * du.y * bc.x);
            Ssum += du.x;
        }
    }
    #undef P1_PRE

    g_E[((size_t)(b*CH + k)*DI + d)*DS + n] = h;
    if (n == 0) g_Ssum[(size_t)(b*CH + k)*DI + d] = Ssum;
}

// =======================================================================
// scan pass 2: compose chunk carries
// =======================================================================
__global__ void __launch_bounds__(256) scan_p2_k(const float* __restrict__ A_logs)
{
    int t = blockIdx.x * 256 + threadIdx.x;
    int n  = t & 15;
    int dd = (t >> 4) % DI;
    int b  = t / (DI*DS);
    float a_coef = -__expf(A_logs[dd*DS + n]);
    float H = 0.f;
    for (int k = 0; k < CH; k++) {
        g_hin[((size_t)(b*CH + k)*DI + dd)*DS + n] = H;
        if (k < CH-1) {
            float S = g_Ssum[(size_t)(b*CH + k)*DI + dd];
            float E = g_E[((size_t)(b*CH + k)*DI + dd)*DS + n];
            H = fmaf(__expf(a_coef * S), H, E);
        }
    }
}

// =======================================================================
// scan pass 3: full scan within chunk, seeded, outputs y
// =======================================================================
__global__ void __launch_bounds__(128) scan_p3_k(const float* __restrict__ A_logs,
        const float* __restrict__ Ds, const int* __restrict__ scan_path)
{
    __shared__ __align__(16) float2 du2[2][TSTEP][8];
    __shared__ __align__(16) float2 bc2[2][TSTEP][DS];
    __shared__ float  ps[TSTEP*8*17];
    __shared__ float  s_D[8];

    int blk = blockIdx.x;
    int k  = blk % CH;
    int cb = blk / CH;
    int b  = cb / 48;
    int d0 = (cb % 48) * 8;
    int tid = threadIdx.x;
    int wid = tid >> 5, lane = tid & 31;
    int g = lane >> 4, n = lane & 15;
    int ch = wid*2 + g;
    int d = d0 + ch;

    float a_coef = -__expf(A_logs[d*DS + n]);
    if (tid < 8) s_D[tid] = Ds[d0 + tid];

    unsigned du_sm = (unsigned)__cvta_generic_to_shared(&du2[0][0][0]);
    unsigned bc_sm = (unsigned)__cvta_generic_to_shared(&bc2[0][0][0]);
    const float2* du_g = g_du + ((size_t)b*LL + k*CL)*DI + d0;
    const float2* bc_g = g_bc + ((size_t)b*LL + k*CL)*DS;

    {
        #pragma unroll
        for (int i = 0; i < 2; i++) {
            int e = tid + 128*i;
            int jj = e >> 3, c = e & 7;
            cpa8(du_sm + (unsigned)((jj*8 + c)*8), du_g + (size_t)jj*DI + c);
        }
        #pragma unroll
        for (int i = 0; i < 2; i++) {
            int e = tid + 128*i;
            int jj = e >> 3, q = e & 7;
            cpa16(bc_sm + (unsigned)((jj*DS + q*2)*8), bc_g + (size_t)jj*DS + q*2);
        }
        cp_commit();
    }

    float h = g_hin[((size_t)(b*CH + k)*DI + d)*DS + n];
    int buf = 0;
    for (int T = 0; T < PTILES; T++) {
        if (T + 1 < PTILES) {
            int o = (buf^1) * TSTEP;
            #pragma unroll
            for (int i = 0; i < 2; i++) {
                int e = tid + 128*i;
                int jj = e >> 3, c = e & 7;
                cpa8(du_sm + (unsigned)(((o+jj)*8 + c)*8),
                     du_g + (size_t)((T+1)*TSTEP + jj)*DI + c);
            }
            #pragma unroll
            for (int i = 0; i < 2; i++) {
                int e = tid + 128*i;
                int jj = e >> 3, q = e & 7;
                cpa16(bc_sm + (unsigned)(((o+jj)*DS + q*2)*8),
                      bc_g + (size_t)((T+1)*TSTEP + jj)*DS + q*2);
            }
            cp_commit();
            cp_wait1();
        } else {
            cp_wait0();
        }
        __syncthreads();

        #pragma unroll 8
        for (int jj = 0; jj < TSTEP; jj++) {
            float2 du = du2[buf][jj][ch];
            float2 bc = bc2[buf][jj][n];
            float dA = __expf(du.x * a_coef);
            h = fmaf(dA, h, du.x * du.y * bc.x);
            ps[(jj*8 + ch)*17 + n] = h * bc.y;
        }
        __syncthreads();

        #pragma unroll
        for (int i = 0; i < 2; i++) {
            int e = tid + 128*i;
            int jj = e >> 3, c = e & 7;
            const float* p = &ps[(jj*8 + c)*17];
            float sum = p[0];
            #pragma unroll
            for (int kk = 1; kk < DS; kk++) sum += p[kk];
            float uval = du2[buf][jj][c].y;
            int pos = __ldg(&scan_path[k*CL + T*TSTEP + jj]);
            g_y[((size_t)b*LL + pos)*DI + d0 + c] = fmaf(uval, s_D[c], sum);
        }
        buf ^= 1;
    }
}

// ---------------- launch ----------------
extern "C" void kernel_launch(void* const* d_in, const int* in_sizes, int n_in,
                              void* d_out, int out_size)
{
    const float* x          = (const float*)d_in[0];
    const float* cond       = (const float*)d_in[1];
    const float* W_in       = (const float*)d_in[2];
    const float* W_con      = (const float*)d_in[3];
    const float* conv_w     = (const float*)d_in[4];
    const float* conv_b     = (const float*)d_in[5];
    const float* con_conv_w = (const float*)d_in[6];
    const float* con_conv_b = (const float*)d_in[7];
    const float* x_proj_w   = (const float*)d_in[8];
    const float* dt_proj_w  = (const float*)d_in[9];
    const float* dt_proj_b  = (const float*)d_in[10];
    const float* A_logs     = (const float*)d_in[11];
    const float* Ds         = (const float*)d_in[12];
    const float* ln_w       = (const float*)d_in[13];
    const float* ln_b       = (const float*)d_in[14];
    const float* W_out      = (const float*)d_in[15];
    const int*   scan_path  = (const int*)d_in[16];
    const int*   rev_scan   = (const int*)d_in[17];
    float* out = (float*)d_out;

    gemm_in_k<<<dim3(3*DI/64, NROWS/128), 256>>>(x, cond, W_in, W_con);
    dwconv_k<<<BB*DI, 256>>>(conv_w, conv_b, con_conv_w, con_conv_b);
    proj1_k<<<NROWS/64, 256>>>(x_proj_w, rev_scan);
    proj2_k<<<512, 256>>>(dt_proj_w, dt_proj_b, rev_scan);
    scan_p1_k<<<96*(CH-1), 128>>>(A_logs);
    scan_p2_k<<<(BB*DI*DS)/256, 256>>>(A_logs);
    scan_p3_k<<<96*CH, 128>>>(A_logs, Ds, scan_path);
    ln_stats_k<<<NROWS/8, 256>>>();
    gemm_out_k<<<dim3(DM/64, NROWS/128), 256>>>(W_out, ln_w, ln_b, out);
}